// round 6
// baseline (speedup 1.0000x reference)
#include <cuda_runtime.h>
#include <cstdint>
#include <cstddef>

// Problem dims (fixed by the reference)
#define D_MODEL 1024
#define SEQ     2048
#define BATCH   2
#define NH      16
#define DK      64
#define DFF     4096
#define MTOT    (BATCH * SEQ)   // 4096 rows

// ---------------------------------------------------------------------------
// Scratch (no allocation allowed -> __device__ globals)
// ---------------------------------------------------------------------------
__device__ float    g_qkv  [3 * MTOT * D_MODEL];   // q | k | v
__device__ uint32_t g_attnT[MTOT * D_MODEL];       // attn out, tf32
__device__ float    g_x1   [MTOT * D_MODEL];
__device__ uint32_t g_x1T  [MTOT * D_MODEL];
__device__ float    g_tmp  [MTOT * D_MODEL];
__device__ uint32_t g_hT   [MTOT * DFF];           // relu(ffn1), tf32
__device__ uint32_t g_xT   [MTOT * D_MODEL];       // x, tf32
__device__ uint32_t g_wqkvT[3 * D_MODEL * D_MODEL];
__device__ uint32_t g_woT  [D_MODEL * D_MODEL];
__device__ uint32_t g_w1T  [D_MODEL * DFF];
__device__ uint32_t g_w2T  [D_MODEL * DFF];

// ---------------------------------------------------------------------------
// helpers
// ---------------------------------------------------------------------------
__device__ __forceinline__ uint32_t f2tf32(float x) {
    uint32_t u;
    asm("cvt.rna.tf32.f32 %0, %1;" : "=r"(u) : "f"(x));
    return u;
}

__device__ __forceinline__ void mma_tf32(float c[4], const uint32_t a[4],
                                         const uint32_t b[2]) {
    asm("mma.sync.aligned.m16n8k8.row.col.f32.tf32.tf32.f32 "
        "{%0,%1,%2,%3}, {%4,%5,%6,%7}, {%8,%9}, {%0,%1,%2,%3};"
        : "+f"(c[0]), "+f"(c[1]), "+f"(c[2]), "+f"(c[3])
        : "r"(a[0]), "r"(a[1]), "r"(a[2]), "r"(a[3]), "r"(b[0]), "r"(b[1]));
}

__device__ __forceinline__ void ldm_x4(uint32_t r[4], uint32_t addr) {
    asm volatile("ldmatrix.sync.aligned.m8n8.x4.shared.b16 {%0,%1,%2,%3}, [%4];"
                 : "=r"(r[0]), "=r"(r[1]), "=r"(r[2]), "=r"(r[3]) : "r"(addr));
}

__device__ __forceinline__ void cp16(uint32_t saddr, const void* gptr) {
    asm volatile("cp.async.cg.shared.global [%0], [%1], 16;"
                 :: "r"(saddr), "l"(gptr));
}
__device__ __forceinline__ void cp_commit() { asm volatile("cp.async.commit_group;"); }
__device__ __forceinline__ void cp_wait2()  { asm volatile("cp.async.wait_group 2;"); }

// ---------------------------------------------------------------------------
// Tensor-core GEMM core. All operands pre-converted tf32.
// A: [M][K] tf32 row-major. WT: [N][K] tf32 (weights pre-transposed).
// Block tile 128x128 x K16, 128 threads = 4 warps (2M x 2N), warp tile 64x64.
// Per warp per K-tile: 16 ldmatrix + 8 cp.async + 64 mma.
// Smem pitch 20 words (ldmatrix row banks (20r)%32 distinct -> conflict-free).
// cp.async 4-stage pipeline. EPI: 0=bias, 1=bias+relu, 2=bias+res.
// ---------------------------------------------------------------------------
#define GP 20
#define ASTG (128 * GP)             // words per tile = 2560
#define STGW (2 * ASTG)             // A+B per stage = 5120 words
#define GSTAGES 4
#define GEMM_SMEM_BYTES (GSTAGES * STGW * 4)   // 81920

template <int EPI, bool TFOUT>
__device__ __forceinline__ void gemm_body(
    const uint32_t* __restrict__ A, const uint32_t* __restrict__ WT,
    const float* __restrict__ bias, const float* __restrict__ res,
    void* __restrict__ Cv, int M, int N, int K, int bm, int bn)
{
    extern __shared__ uint32_t gsm[];

    const int tid  = threadIdx.x;
    const int wid  = tid >> 5;
    const int lane = tid & 31;
    const int g    = lane >> 2;
    const int t    = lane & 3;
    const int wm   = (wid & 1) * 64;
    const int wn   = (wid >> 1) * 64;

    float acc[4][8][4];
#pragma unroll
    for (int i = 0; i < 4; i++)
#pragma unroll
        for (int j = 0; j < 8; j++)
#pragma unroll
            for (int e = 0; e < 4; e++) acc[i][j][e] = 0.f;

    // cp.async: tile = 128 rows x 4 16B-chunks; 128 threads -> 32 rows/pass, x4
    const int cr = tid >> 2, cc = (tid & 3) * 4;
    const uint32_t sbase = (uint32_t)__cvta_generic_to_shared(gsm);
    const uint32_t aS = sbase + (cr * GP + cc) * 4;
    const uint32_t bS = aS + ASTG * 4;
    const uint32_t* aG0 = A  + (size_t)(bm + cr) * K + cc;
    const uint32_t* bG0 = WT + (size_t)(bn + cr) * K + cc;

#define GI(kt)                                                                 \
    {                                                                          \
        const uint32_t so_ = ((kt) & 3) * (STGW * 4);                          \
        const int k0_ = (kt) * 16;                                             \
        _Pragma("unroll")                                                      \
        for (int ro = 0; ro < 128; ro += 32) {                                 \
            cp16(aS + so_ + ro * GP * 4, aG0 + (size_t)ro * K + k0_);          \
            cp16(bS + so_ + ro * GP * 4, bG0 + (size_t)ro * K + k0_);          \
        }                                                                      \
    }

    // ldmatrix per-lane addresses (A-map and B-map proven in R5)
    const int lrow = lane & 7, lsel = lane >> 3;
    const int a_ro = (lsel & 1) * 8 + lrow;
    const int a_co = (lsel >> 1) * 4;
    uint32_t a_lm[4];
#pragma unroll
    for (int mt = 0; mt < 4; mt++)
        a_lm[mt] = sbase + ((wm + mt * 16 + a_ro) * GP + a_co) * 4;
    const int b_ro = (lsel >> 1) * 8 + lrow;
    const int b_co = (lsel & 1) * 4;
    uint32_t b_lm[4];
#pragma unroll
    for (int p = 0; p < 4; p++)
        b_lm[p] = sbase + ASTG * 4 + ((wn + p * 16 + b_ro) * GP + b_co) * 4;

    const int nk = K >> 4;
#pragma unroll
    for (int s = 0; s < GSTAGES - 1; s++) { GI(s) cp_commit(); }

    for (int kt = 0; kt < nk; kt++) {
        cp_wait2();
        __syncthreads();
        if (kt + GSTAGES - 1 < nk) { GI(kt + GSTAGES - 1) }
        cp_commit();

        const uint32_t so = (kt & 3) * (STGW * 4);
#pragma unroll
        for (int ks = 0; ks < 16; ks += 8) {
            uint32_t af[4][4];
#pragma unroll
            for (int mt = 0; mt < 4; mt++)
                ldm_x4(af[mt], a_lm[mt] + so + ks * 4);
            uint32_t bf[4][4];
#pragma unroll
            for (int p = 0; p < 4; p++)
                ldm_x4(bf[p], b_lm[p] + so + ks * 4);
#pragma unroll
            for (int mt = 0; mt < 4; mt++)
#pragma unroll
                for (int nt = 0; nt < 8; nt++)
                    mma_tf32(acc[mt][nt], af[mt], &bf[nt >> 1][(nt & 1) * 2]);
        }
    }
#undef GI

    // epilogue
#pragma unroll
    for (int mt = 0; mt < 4; mt++) {
        const int r = bm + wm + mt * 16 + g;
#pragma unroll
        for (int nt = 0; nt < 8; nt++) {
            const int c = bn + wn + nt * 8 + 2 * t;
            const float2 bb = *(const float2*)(bias + c);
            float2 v0, v1;
            v0.x = acc[mt][nt][0] + bb.x;  v0.y = acc[mt][nt][1] + bb.y;
            v1.x = acc[mt][nt][2] + bb.x;  v1.y = acc[mt][nt][3] + bb.y;
            if (EPI == 1) {
                v0.x = fmaxf(v0.x, 0.f); v0.y = fmaxf(v0.y, 0.f);
                v1.x = fmaxf(v1.x, 0.f); v1.y = fmaxf(v1.y, 0.f);
            }
            if (EPI == 2) {
                const float2 r0 = *(const float2*)(res + (size_t)r * N + c);
                const float2 r1 = *(const float2*)(res + (size_t)(r + 8) * N + c);
                v0.x += r0.x; v0.y += r0.y;
                v1.x += r1.x; v1.y += r1.y;
            }
            if (TFOUT) {
                uint32_t* C = (uint32_t*)Cv;
                uint2 u0 = make_uint2(f2tf32(v0.x), f2tf32(v0.y));
                uint2 u1 = make_uint2(f2tf32(v1.x), f2tf32(v1.y));
                *(uint2*)(C + (size_t)r * N + c)       = u0;
                *(uint2*)(C + (size_t)(r + 8) * N + c) = u1;
            } else {
                float* C = (float*)Cv;
                *(float2*)(C + (size_t)r * N + c)       = v0;
                *(float2*)(C + (size_t)(r + 8) * N + c) = v1;
            }
        }
    }
}

template <int EPI, bool TFOUT>
__global__ __launch_bounds__(128, 2)
void gemm_tc(const uint32_t* __restrict__ A, const uint32_t* __restrict__ WT,
             const float* __restrict__ bias, const float* __restrict__ res,
             void* __restrict__ C, int M, int N, int K)
{
    gemm_body<EPI, TFOUT>(A, WT, bias, res, C, M, N, K,
                          blockIdx.y * 128, blockIdx.x * 128);
}

// fused QKV: gridDim.z = 3 selects weight slab / bias / output slab
__global__ __launch_bounds__(128, 2)
void qkv_tc(const uint32_t* __restrict__ xT, const uint32_t* __restrict__ wqkvT,
            const float* __restrict__ bq, const float* __restrict__ bk,
            const float* __restrict__ bv, float* __restrict__ qkv)
{
    const int z = blockIdx.z;
    const float* bias = (z == 0) ? bq : (z == 1) ? bk : bv;
    gemm_body<0, false>(xT, wqkvT + (size_t)z * D_MODEL * D_MODEL, bias, nullptr,
                        qkv + (size_t)z * MTOT * D_MODEL,
                        MTOT, D_MODEL, D_MODEL, blockIdx.y * 128, blockIdx.x * 128);
}

// ---------------------------------------------------------------------------
// Pre-pass: transpose + tf32-convert weights; convert x.
// ---------------------------------------------------------------------------
__device__ __forceinline__ void transp_body(const float* __restrict__ W,
                                            uint32_t* __restrict__ WT, int K, int N)
{
    __shared__ float tl[32][33];
    const int n0 = blockIdx.x * 32, k0 = blockIdx.y * 32;
    const int tx = threadIdx.x, ty = threadIdx.y;
#pragma unroll
    for (int i = 0; i < 32; i += 8)
        tl[ty + i][tx] = W[(size_t)(k0 + ty + i) * N + n0 + tx];
    __syncthreads();
#pragma unroll
    for (int i = 0; i < 32; i += 8)
        WT[(size_t)(n0 + ty + i) * K + k0 + tx] = f2tf32(tl[tx][ty + i]);
}

__global__ void transp_qkvo(const float* __restrict__ wq, const float* __restrict__ wk,
                            const float* __restrict__ wv, const float* __restrict__ wo,
                            uint32_t* __restrict__ qkvT, uint32_t* __restrict__ woT)
{
    const int z = blockIdx.z;
    const float* W = (z == 0) ? wq : (z == 1) ? wk : (z == 2) ? wv : wo;
    uint32_t* WT = (z < 3) ? qkvT + (size_t)z * D_MODEL * D_MODEL : woT;
    transp_body(W, WT, D_MODEL, D_MODEL);
}

__global__ void transp_gen(const float* __restrict__ W, uint32_t* __restrict__ WT,
                           int K, int N)
{
    transp_body(W, WT, K, N);
}

__global__ void cvt_tf32_vec(const float* __restrict__ X, uint32_t* __restrict__ Y)
{
    const int i = blockIdx.x * blockDim.x + threadIdx.x;
    float4 v = ((const float4*)X)[i];
    uint4 u;
    u.x = f2tf32(v.x); u.y = f2tf32(v.y); u.z = f2tf32(v.z); u.w = f2tf32(v.w);
    ((uint4*)Y)[i] = u;
}

// ---------------------------------------------------------------------------
// Tensor-core flash attention (tf32 mma). QK a/b-frags and PV a-frags now via
// ldmatrix (same lane maps as the GEMM); PV b-frags remain scalar LDS.
// ---------------------------------------------------------------------------
#define AQT 128
#define AKT 64
#define QP  68
#define KP  68
#define VP  72
#define PP  68
#define QS_OFF 0
#define KS_OFF (AQT * QP)
#define VS_OFF (KS_OFF + AKT * KP)
#define PS_OFF (VS_OFF + AKT * VP)
#define ATTN_SMEM_BYTES ((PS_OFF + AQT * PP) * 4)

__global__ __launch_bounds__(256, 2)
void attn_tc(const float* __restrict__ Q, const float* __restrict__ K,
             const float* __restrict__ V, uint32_t* __restrict__ O)
{
    extern __shared__ uint32_t asmem[];
    uint32_t* qs = asmem + QS_OFF;
    uint32_t* ks = asmem + KS_OFF;
    uint32_t* vs = asmem + VS_OFF;
    uint32_t* ps = asmem + PS_OFF;

    const int tid  = threadIdx.x;
    const int wid  = tid >> 5;
    const int lane = tid & 31;
    const int g    = lane >> 2;
    const int t    = lane & 3;
    const int bh   = blockIdx.y;
    const int b    = bh >> 4;
    const int h    = bh & 15;
    const int q0   = blockIdx.x * AQT;
    const size_t base = (size_t)b * SEQ * D_MODEL + (size_t)h * DK;

#pragma unroll
    for (int e = 0; e < 8; e++) {
        int idx = tid + 256 * e;
        int r = idx >> 4, c4 = (idx & 15) * 4;
        float4 qv = *(const float4*)(Q + base + (size_t)(q0 + r) * D_MODEL + c4);
        qs[r * QP + c4 + 0] = f2tf32(qv.x * 0.125f);
        qs[r * QP + c4 + 1] = f2tf32(qv.y * 0.125f);
        qs[r * QP + c4 + 2] = f2tf32(qv.z * 0.125f);
        qs[r * QP + c4 + 3] = f2tf32(qv.w * 0.125f);
    }

    float m0 = -1e30f, m1 = -1e30f, l0 = 0.f, l1 = 0.f;
    float oacc[8][4];
#pragma unroll
    for (int nt = 0; nt < 8; nt++)
#pragma unroll
        for (int e = 0; e < 4; e++) oacc[nt][e] = 0.f;

    const int qrow = wid * 16;

    // ldmatrix lane addresses
    const uint32_t sbase = (uint32_t)__cvta_generic_to_shared(asmem);
    const int lrow = lane & 7, lsel = lane >> 3;
    const int a_ro = (lsel & 1) * 8 + lrow;
    const int a_co = (lsel >> 1) * 4;
    const int b_ro = (lsel >> 1) * 8 + lrow;
    const int b_co = (lsel & 1) * 4;
    const uint32_t q_lm = sbase + ((QS_OFF + (qrow + a_ro) * QP + a_co)) * 4;
    const uint32_t p_lm = sbase + ((PS_OFF + (qrow + a_ro) * PP + a_co)) * 4;
    uint32_t k_lm[4];
#pragma unroll
    for (int p = 0; p < 4; p++)
        k_lm[p] = sbase + ((KS_OFF + (p * 16 + b_ro) * KP + b_co)) * 4;

    for (int k0 = 0; k0 < SEQ; k0 += AKT) {
        __syncthreads();
#pragma unroll
        for (int e = 0; e < 4; e++) {
            int idx = tid + 256 * e;
            int r = idx >> 4, c4 = (idx & 15) * 4;
            float4 kv = *(const float4*)(K + base + (size_t)(k0 + r) * D_MODEL + c4);
            ks[r * KP + c4 + 0] = f2tf32(kv.x);
            ks[r * KP + c4 + 1] = f2tf32(kv.y);
            ks[r * KP + c4 + 2] = f2tf32(kv.z);
            ks[r * KP + c4 + 3] = f2tf32(kv.w);
            float4 vv = *(const float4*)(V + base + (size_t)(k0 + r) * D_MODEL + c4);
            vs[r * VP + c4 + 0] = f2tf32(vv.x);
            vs[r * VP + c4 + 1] = f2tf32(vv.y);
            vs[r * VP + c4 + 2] = f2tf32(vv.z);
            vs[r * VP + c4 + 3] = f2tf32(vv.w);
        }
        __syncthreads();

        // ---- S = Q K^T ----
        float sacc[8][4];
#pragma unroll
        for (int nt = 0; nt < 8; nt++)
#pragma unroll
            for (int e = 0; e < 4; e++) sacc[nt][e] = 0.f;

#pragma unroll
        for (int k8 = 0; k8 < 8; k8++) {
            uint32_t a[4];
            ldm_x4(a, q_lm + k8 * 32);
            uint32_t bf[4][4];
#pragma unroll
            for (int p = 0; p < 4; p++)
                ldm_x4(bf[p], k_lm[p] + k8 * 32);
#pragma unroll
            for (int nt = 0; nt < 8; nt++)
                mma_tf32(sacc[nt], a, &bf[nt >> 1][(nt & 1) * 2]);
        }

        // ---- online softmax ----
        float rmax0 = -1e30f, rmax1 = -1e30f;
#pragma unroll
        for (int nt = 0; nt < 8; nt++) {
            rmax0 = fmaxf(rmax0, fmaxf(sacc[nt][0], sacc[nt][1]));
            rmax1 = fmaxf(rmax1, fmaxf(sacc[nt][2], sacc[nt][3]));
        }
        rmax0 = fmaxf(rmax0, __shfl_xor_sync(0xffffffffu, rmax0, 1));
        rmax0 = fmaxf(rmax0, __shfl_xor_sync(0xffffffffu, rmax0, 2));
        rmax1 = fmaxf(rmax1, __shfl_xor_sync(0xffffffffu, rmax1, 1));
        rmax1 = fmaxf(rmax1, __shfl_xor_sync(0xffffffffu, rmax1, 2));

        const float nm0 = fmaxf(m0, rmax0);
        const float nm1 = fmaxf(m1, rmax1);
        const float sc0 = __expf(m0 - nm0);
        const float sc1 = __expf(m1 - nm1);

        float rs0 = 0.f, rs1 = 0.f;
#pragma unroll
        for (int nt = 0; nt < 8; nt++) {
            float p00 = __expf(sacc[nt][0] - nm0);
            float p01 = __expf(sacc[nt][1] - nm0);
            float p10 = __expf(sacc[nt][2] - nm1);
            float p11 = __expf(sacc[nt][3] - nm1);
            rs0 += p00 + p01;
            rs1 += p10 + p11;
            ps[(qrow + g    ) * PP + nt * 8 + 2 * t    ] = f2tf32(p00);
            ps[(qrow + g    ) * PP + nt * 8 + 2 * t + 1] = f2tf32(p01);
            ps[(qrow + g + 8) * PP + nt * 8 + 2 * t    ] = f2tf32(p10);
            ps[(qrow + g + 8) * PP + nt * 8 + 2 * t + 1] = f2tf32(p11);
        }
        rs0 += __shfl_xor_sync(0xffffffffu, rs0, 1);
        rs0 += __shfl_xor_sync(0xffffffffu, rs0, 2);
        rs1 += __shfl_xor_sync(0xffffffffu, rs1, 1);
        rs1 += __shfl_xor_sync(0xffffffffu, rs1, 2);

        m0 = nm0; m1 = nm1;
        l0 = l0 * sc0 + rs0;
        l1 = l1 * sc1 + rs1;
#pragma unroll
        for (int nt = 0; nt < 8; nt++) {
            oacc[nt][0] *= sc0; oacc[nt][1] *= sc0;
            oacc[nt][2] *= sc1; oacc[nt][3] *= sc1;
        }

        __syncwarp();

        // ---- O += P V ----
#pragma unroll
        for (int k8 = 0; k8 < 8; k8++) {
            uint32_t a[4];
            ldm_x4(a, p_lm + k8 * 32);
#pragma unroll
            for (int nt = 0; nt < 8; nt++) {
                uint32_t bb[2];
                bb[0] = vs[(k8 * 8 + t    ) * VP + nt * 8 + g];
                bb[1] = vs[(k8 * 8 + t + 4) * VP + nt * 8 + g];
                mma_tf32(oacc[nt], a, bb);
            }
        }
    }

    const float il0 = 1.f / l0;
    const float il1 = 1.f / l1;
#pragma unroll
    for (int nt = 0; nt < 8; nt++) {
        const int c = nt * 8 + 2 * t;
        uint2 u0, u1;
        u0.x = f2tf32(oacc[nt][0] * il0);  u0.y = f2tf32(oacc[nt][1] * il0);
        u1.x = f2tf32(oacc[nt][2] * il1);  u1.y = f2tf32(oacc[nt][3] * il1);
        *(uint2*)(O + base + (size_t)(q0 + qrow + g    ) * D_MODEL + c) = u0;
        *(uint2*)(O + base + (size_t)(q0 + qrow + g + 8) * D_MODEL + c) = u1;
    }
}

// ---------------------------------------------------------------------------
// LayerNorm over last dim (1024); optional tf32 copy output.
// ---------------------------------------------------------------------------
__global__ __launch_bounds__(256)
void ln_kernel(const float* __restrict__ X, const float* __restrict__ g,
               const float* __restrict__ b, float* __restrict__ Y,
               uint32_t* __restrict__ Ytf)
{
    const int row = blockIdx.x;
    const float* x = X + (size_t)row * D_MODEL;

    float v[4];
    float s = 0.f, s2 = 0.f;
#pragma unroll
    for (int e = 0; e < 4; e++) {
        v[e] = x[threadIdx.x + 256 * e];
        s  += v[e];
        s2 += v[e] * v[e];
    }
#pragma unroll
    for (int off = 16; off; off >>= 1) {
        s  += __shfl_xor_sync(0xffffffffu, s,  off);
        s2 += __shfl_xor_sync(0xffffffffu, s2, off);
    }
    __shared__ float rs[8], rs2[8];
    const int w = threadIdx.x >> 5, lane = threadIdx.x & 31;
    if (lane == 0) { rs[w] = s; rs2[w] = s2; }
    __syncthreads();
    s = 0.f; s2 = 0.f;
#pragma unroll
    for (int i = 0; i < 8; i++) { s += rs[i]; s2 += rs2[i]; }

    const float mean = s * (1.f / D_MODEL);
    const float var  = s2 * (1.f / D_MODEL) - mean * mean;
    const float rstd = rsqrtf(var + 1e-5f);

    float* y = Y + (size_t)row * D_MODEL;
#pragma unroll
    for (int e = 0; e < 4; e++) {
        int c = threadIdx.x + 256 * e;
        float val = (v[e] - mean) * rstd * g[c] + b[c];
        y[c] = val;
        if (Ytf) Ytf[(size_t)row * D_MODEL + c] = f2tf32(val);
    }
}

// ---------------------------------------------------------------------------
// Launch
// ---------------------------------------------------------------------------
extern "C" void kernel_launch(void* const* d_in, const int* in_sizes, int n_in,
                              void* d_out, int out_size)
{
    const float* x     = (const float*)d_in[0];
    const float* wq    = (const float*)d_in[1];
    const float* bq    = (const float*)d_in[2];
    const float* wk    = (const float*)d_in[3];
    const float* bk    = (const float*)d_in[4];
    const float* wv    = (const float*)d_in[5];
    const float* bv    = (const float*)d_in[6];
    const float* wo    = (const float*)d_in[7];
    const float* bo    = (const float*)d_in[8];
    const float* ln1_g = (const float*)d_in[9];
    const float* ln1_b = (const float*)d_in[10];
    const float* ln2_g = (const float*)d_in[11];
    const float* ln2_b = (const float*)d_in[12];
    const float* w1    = (const float*)d_in[13];
    const float* b1    = (const float*)d_in[14];
    const float* w2    = (const float*)d_in[15];
    const float* b2    = (const float*)d_in[16];
    float* out = (float*)d_out;

    float *qkv, *x1, *tmp;
    uint32_t *attnT, *x1T, *hT, *xT, *wqkvT, *woT, *w1T, *w2T;
    cudaGetSymbolAddress((void**)&qkv,   g_qkv);
    cudaGetSymbolAddress((void**)&attnT, g_attnT);
    cudaGetSymbolAddress((void**)&x1,    g_x1);
    cudaGetSymbolAddress((void**)&x1T,   g_x1T);
    cudaGetSymbolAddress((void**)&tmp,   g_tmp);
    cudaGetSymbolAddress((void**)&hT,    g_hT);
    cudaGetSymbolAddress((void**)&xT,    g_xT);
    cudaGetSymbolAddress((void**)&wqkvT, g_wqkvT);
    cudaGetSymbolAddress((void**)&woT,   g_woT);
    cudaGetSymbolAddress((void**)&w1T,   g_w1T);
    cudaGetSymbolAddress((void**)&w2T,   g_w2T);

    cudaFuncSetAttribute(attn_tc, cudaFuncAttributeMaxDynamicSharedMemorySize,
                         ATTN_SMEM_BYTES);
    cudaFuncSetAttribute(qkv_tc, cudaFuncAttributeMaxDynamicSharedMemorySize,
                         GEMM_SMEM_BYTES);
    cudaFuncSetAttribute(gemm_tc<2, false>, cudaFuncAttributeMaxDynamicSharedMemorySize,
                         GEMM_SMEM_BYTES);
    cudaFuncSetAttribute(gemm_tc<1, true>, cudaFuncAttributeMaxDynamicSharedMemorySize,
                         GEMM_SMEM_BYTES);

    const dim3 gblk(128);
    const dim3 blk(256);
    const dim3 tblk(32, 8);

    // pre-pass: convert x; transpose+convert weights
    cvt_tf32_vec<<<MTOT * D_MODEL / 4 / 256, blk>>>(x, xT);
    transp_qkvo<<<dim3(32, 32, 4), tblk>>>(wq, wk, wv, wo, wqkvT, woT);
    transp_gen<<<dim3(DFF / 32, D_MODEL / 32), tblk>>>(w1, w1T, D_MODEL, DFF);
    transp_gen<<<dim3(D_MODEL / 32, DFF / 32), tblk>>>(w2, w2T, DFF, D_MODEL);

    // QKV (fused, z = 0/1/2)
    qkv_tc<<<dim3(D_MODEL / 128, MTOT / 128, 3), gblk, GEMM_SMEM_BYTES>>>(
        xT, wqkvT, bq, bk, bv, qkv);

    // attention
    attn_tc<<<dim3(SEQ / AQT, BATCH * NH), blk, ATTN_SMEM_BYTES>>>(
        qkv, qkv + (size_t)MTOT * D_MODEL, qkv + (size_t)2 * MTOT * D_MODEL, attnT);

    // O-proj + residual -> LN1
    gemm_tc<2, false><<<dim3(D_MODEL / 128, MTOT / 128), gblk, GEMM_SMEM_BYTES>>>(
        attnT, woT, bo, x, tmp, MTOT, D_MODEL, D_MODEL);
    ln_kernel<<<MTOT, blk>>>(tmp, ln1_g, ln1_b, x1, x1T);

    // FFN
    gemm_tc<1, true><<<dim3(DFF / 128, MTOT / 128), gblk, GEMM_SMEM_BYTES>>>(
        x1T, w1T, b1, nullptr, hT, MTOT, DFF, D_MODEL);
    gemm_tc<2, false><<<dim3(D_MODEL / 128, MTOT / 128), gblk, GEMM_SMEM_BYTES>>>(
        hT, w2T, b2, x1, tmp, MTOT, D_MODEL, DFF);
    ln_kernel<<<MTOT, blk>>>(tmp, ln2_g, ln2_b, out, nullptr);
}

// round 8
// speedup vs baseline: 1.8597x; 1.8597x over previous
#include <cuda_runtime.h>
#include <cuda_fp16.h>
#include <cstdint>
#include <cstddef>

// Problem dims (fixed by the reference)
#define D_MODEL 1024
#define SEQ     2048
#define BATCH   2
#define NH      16
#define DK      64
#define DFF     4096
#define MTOT    (BATCH * SEQ)   // 4096 rows

// ---------------------------------------------------------------------------
// Scratch (no allocation allowed -> __device__ globals)
// ---------------------------------------------------------------------------
__device__ __half g_qkvH [3 * MTOT * D_MODEL];  // q|k|v, fp16 (q pre-scaled by 1/8)
__device__ __half g_attnH[MTOT * D_MODEL];      // attn out, fp16
__device__ float  g_x1   [MTOT * D_MODEL];
__device__ __half g_x1H  [MTOT * D_MODEL];
__device__ float  g_tmp  [MTOT * D_MODEL];
__device__ __half g_hH   [MTOT * DFF];          // relu(ffn1), fp16
__device__ __half g_xH   [MTOT * D_MODEL];      // x, fp16
__device__ __half g_wqkvH[3 * D_MODEL * D_MODEL];
__device__ __half g_woH  [D_MODEL * D_MODEL];
__device__ __half g_w1H  [D_MODEL * DFF];
__device__ __half g_w2H  [D_MODEL * DFF];

// ---------------------------------------------------------------------------
// helpers
// ---------------------------------------------------------------------------
__device__ __forceinline__ void mma_f16(float c[4], const uint32_t a[4],
                                        const uint32_t b[2]) {
    asm("mma.sync.aligned.m16n8k16.row.col.f32.f16.f16.f32 "
        "{%0,%1,%2,%3}, {%4,%5,%6,%7}, {%8,%9}, {%0,%1,%2,%3};"
        : "+f"(c[0]), "+f"(c[1]), "+f"(c[2]), "+f"(c[3])
        : "r"(a[0]), "r"(a[1]), "r"(a[2]), "r"(a[3]), "r"(b[0]), "r"(b[1]));
}

__device__ __forceinline__ void ldm_x4(uint32_t r[4], uint32_t addr) {
    asm volatile("ldmatrix.sync.aligned.m8n8.x4.shared.b16 {%0,%1,%2,%3}, [%4];"
                 : "=r"(r[0]), "=r"(r[1]), "=r"(r[2]), "=r"(r[3]) : "r"(addr));
}
__device__ __forceinline__ void ldm_x4_t(uint32_t r[4], uint32_t addr) {
    asm volatile("ldmatrix.sync.aligned.m8n8.x4.trans.shared.b16 {%0,%1,%2,%3}, [%4];"
                 : "=r"(r[0]), "=r"(r[1]), "=r"(r[2]), "=r"(r[3]) : "r"(addr));
}

__device__ __forceinline__ void cp16(uint32_t saddr, const void* gptr) {
    asm volatile("cp.async.cg.shared.global [%0], [%1], 16;"
                 :: "r"(saddr), "l"(gptr));
}
__device__ __forceinline__ void cp_commit() { asm volatile("cp.async.commit_group;"); }
__device__ __forceinline__ void cp_wait2()  { asm volatile("cp.async.wait_group 2;"); }

// ---------------------------------------------------------------------------
// fp16 tensor-core GEMM. A: [M][K] fp16 row-major. WT: [N][K] fp16.
// Block tile 128x128 x K32(halves), 256 threads = 8 warps (2M x 4N),
// warp tile 64x32, mma m16n8k16, ldmatrix.x4 fragments.
// Smem pitch 40 halves (80B): row-start banks 20r mod 32 bijective over 8 rows
// -> conflict-free ldmatrix. cp.async 4-stage pipeline (R5-proven ordering).
// EPI: 0=bias, 1=bias+relu, 2=bias+res. OUTH: write fp16. oscale applied
// after bias (used to fold attention's 1/sqrt(dk) into Q).
// ---------------------------------------------------------------------------
#define GP 40                      // halves per smem row
#define TILE_B (128 * GP * 2)      // bytes per tile = 10240
#define STG_B  (2 * TILE_B)        // A+B per stage = 20480
#define GSTAGES 4
#define GEMM_SMEM (GSTAGES * STG_B)   // 81920

template <int EPI, int OUTH>
__device__ __forceinline__ void gemm_body(
    const __half* __restrict__ A, const __half* __restrict__ WT,
    const float* __restrict__ bias, const float* __restrict__ res,
    void* __restrict__ Cv, int N, int K, int bm, int bn, float oscale)
{
    extern __shared__ uint32_t gsm[];

    const int tid  = threadIdx.x;
    const int wid  = tid >> 5;
    const int lane = tid & 31;
    const int g    = lane >> 2;
    const int t    = lane & 3;
    const int wm   = (wid & 1) * 64;
    const int wn   = (wid >> 1) * 32;

    float acc[4][4][4];
#pragma unroll
    for (int i = 0; i < 4; i++)
#pragma unroll
        for (int j = 0; j < 4; j++)
#pragma unroll
            for (int e = 0; e < 4; e++) acc[i][j][e] = 0.f;

    // cp.async: tile = 128 rows x 4 chunks (8 halves); thread -> 2 rows per tile
    const int r0 = tid >> 2,         c0 = tid & 3;
    const int r1 = (tid + 256) >> 2, c1 = (tid + 256) & 3;
    const uint32_t sbase = (uint32_t)__cvta_generic_to_shared(gsm);
    const uint32_t aS0 = sbase + (uint32_t)(r0 * GP + c0 * 8) * 2;
    const uint32_t aS1 = sbase + (uint32_t)(r1 * GP + c1 * 8) * 2;
    const uint32_t bS0 = aS0 + TILE_B;
    const uint32_t bS1 = aS1 + TILE_B;
    const __half* aG0 = A  + (size_t)(bm + r0) * K + c0 * 8;
    const __half* aG1 = A  + (size_t)(bm + r1) * K + c1 * 8;
    const __half* bG0 = WT + (size_t)(bn + r0) * K + c0 * 8;
    const __half* bG1 = WT + (size_t)(bn + r1) * K + c1 * 8;

#define GI(kt)                                                                 \
    {                                                                          \
        const uint32_t so_ = ((kt) & 3) * STG_B;                               \
        const int k0_ = (kt) * 32;                                             \
        cp16(aS0 + so_, aG0 + k0_);                                            \
        cp16(aS1 + so_, aG1 + k0_);                                            \
        cp16(bS0 + so_, bG0 + k0_);                                            \
        cp16(bS1 + so_, bG1 + k0_);                                            \
    }

    // ldmatrix lane addresses (canonical x4 <-> m16n8k16 pairing)
    const int lr = lane & 7, sel = lane >> 3;
    const int aro = (sel & 1) * 8 + lr, aco = (sel >> 1) * 8;
    uint32_t a_lm[4];
#pragma unroll
    for (int mt = 0; mt < 4; mt++)
        a_lm[mt] = sbase + (uint32_t)((wm + mt * 16 + aro) * GP + aco) * 2;
    const int bro = (sel >> 1) * 8 + lr, bco = (sel & 1) * 8;
    uint32_t b_lm[2];
#pragma unroll
    for (int p = 0; p < 2; p++)
        b_lm[p] = sbase + TILE_B + (uint32_t)((wn + p * 16 + bro) * GP + bco) * 2;

    const int nk = K >> 5;
#pragma unroll
    for (int s = 0; s < GSTAGES - 1; s++) { GI(s) cp_commit(); }

    for (int kt = 0; kt < nk; kt++) {
        cp_wait2();
        __syncthreads();
        if (kt + GSTAGES - 1 < nk) { GI(kt + GSTAGES - 1) }
        cp_commit();

        const uint32_t so = (kt & 3) * STG_B;
#pragma unroll
        for (int ks = 0; ks < 2; ks++) {
            uint32_t af[4][4];
#pragma unroll
            for (int mt = 0; mt < 4; mt++)
                ldm_x4(af[mt], a_lm[mt] + so + ks * 32);
            uint32_t bf[2][4];
            ldm_x4(bf[0], b_lm[0] + so + ks * 32);
            ldm_x4(bf[1], b_lm[1] + so + ks * 32);
#pragma unroll
            for (int mt = 0; mt < 4; mt++)
#pragma unroll
                for (int nt = 0; nt < 4; nt++)
                    mma_f16(acc[mt][nt], af[mt], &bf[nt >> 1][(nt & 1) * 2]);
        }
    }
#undef GI

    // epilogue (layout identical to m16n8k8: rows g/g+8, cols 2t,2t+1)
#pragma unroll
    for (int mt = 0; mt < 4; mt++) {
        const int r = bm + wm + mt * 16 + g;
#pragma unroll
        for (int nt = 0; nt < 4; nt++) {
            const int c = bn + wn + nt * 8 + 2 * t;
            const float2 bb = *(const float2*)(bias + c);
            float2 v0, v1;
            v0.x = (acc[mt][nt][0] + bb.x) * oscale;
            v0.y = (acc[mt][nt][1] + bb.y) * oscale;
            v1.x = (acc[mt][nt][2] + bb.x) * oscale;
            v1.y = (acc[mt][nt][3] + bb.y) * oscale;
            if (EPI == 1) {
                v0.x = fmaxf(v0.x, 0.f); v0.y = fmaxf(v0.y, 0.f);
                v1.x = fmaxf(v1.x, 0.f); v1.y = fmaxf(v1.y, 0.f);
            }
            if (EPI == 2) {
                const float2 q0r = *(const float2*)(res + (size_t)r * N + c);
                const float2 q1r = *(const float2*)(res + (size_t)(r + 8) * N + c);
                v0.x += q0r.x; v0.y += q0r.y;
                v1.x += q1r.x; v1.y += q1r.y;
            }
            if (OUTH) {
                __half* C = (__half*)Cv;
                *(__half2*)(C + (size_t)r * N + c)       = __floats2half2_rn(v0.x, v0.y);
                *(__half2*)(C + (size_t)(r + 8) * N + c) = __floats2half2_rn(v1.x, v1.y);
            } else {
                float* C = (float*)Cv;
                *(float2*)(C + (size_t)r * N + c)       = v0;
                *(float2*)(C + (size_t)(r + 8) * N + c) = v1;
            }
        }
    }
}

template <int EPI, int OUTH>
__global__ __launch_bounds__(256, 2)
void gemm_tc(const __half* __restrict__ A, const __half* __restrict__ WT,
             const float* __restrict__ bias, const float* __restrict__ res,
             void* __restrict__ C, int N, int K)
{
    gemm_body<EPI, OUTH>(A, WT, bias, res, C, N, K,
                         blockIdx.y * 128, blockIdx.x * 128, 1.f);
}

// fused QKV: gridDim.z = 3; Q output pre-scaled by 1/sqrt(DK) = 0.125
__global__ __launch_bounds__(256, 2)
void qkv_tc(const __half* __restrict__ xH, const __half* __restrict__ wqkvH,
            const float* __restrict__ bq, const float* __restrict__ bk,
            const float* __restrict__ bv, __half* __restrict__ qkvH)
{
    const int z = blockIdx.z;
    const float* bias = (z == 0) ? bq : (z == 1) ? bk : bv;
    gemm_body<0, 1>(xH, wqkvH + (size_t)z * D_MODEL * D_MODEL, bias, nullptr,
                    qkvH + (size_t)z * MTOT * D_MODEL, D_MODEL, D_MODEL,
                    blockIdx.y * 128, blockIdx.x * 128,
                    (z == 0) ? 0.125f : 1.f);
}

// ---------------------------------------------------------------------------
// Pre-pass: transpose + fp16-convert weights; convert x.
// ---------------------------------------------------------------------------
__device__ __forceinline__ void transp_body(const float* __restrict__ W,
                                            __half* __restrict__ WT, int K, int N)
{
    __shared__ float tl[32][33];
    const int n0 = blockIdx.x * 32, k0 = blockIdx.y * 32;
    const int tx = threadIdx.x, ty = threadIdx.y;
#pragma unroll
    for (int i = 0; i < 32; i += 8)
        tl[ty + i][tx] = W[(size_t)(k0 + ty + i) * N + n0 + tx];
    __syncthreads();
#pragma unroll
    for (int i = 0; i < 32; i += 8)
        WT[(size_t)(n0 + ty + i) * K + k0 + tx] = __float2half_rn(tl[tx][ty + i]);
}

__global__ void transp_qkvo(const float* __restrict__ wq, const float* __restrict__ wk,
                            const float* __restrict__ wv, const float* __restrict__ wo,
                            __half* __restrict__ qkvT, __half* __restrict__ woT)
{
    const int z = blockIdx.z;
    const float* W = (z == 0) ? wq : (z == 1) ? wk : (z == 2) ? wv : wo;
    __half* WT = (z < 3) ? qkvT + (size_t)z * D_MODEL * D_MODEL : woT;
    transp_body(W, WT, D_MODEL, D_MODEL);
}

__global__ void transp_gen(const float* __restrict__ W, __half* __restrict__ WT,
                           int K, int N)
{
    transp_body(W, WT, K, N);
}

__global__ void cvt_f16_vec(const float* __restrict__ X, __half* __restrict__ Y)
{
    const int i = blockIdx.x * blockDim.x + threadIdx.x;
    float4 v = ((const float4*)X)[i];
    __half2 h0 = __floats2half2_rn(v.x, v.y);
    __half2 h1 = __floats2half2_rn(v.z, v.w);
    uint2 u;
    u.x = *(uint32_t*)&h0;
    u.y = *(uint32_t*)&h1;
    ((uint2*)Y)[i] = u;
}

// ---------------------------------------------------------------------------
// fp16 tensor-core flash attention (m16n8k16 mma).
// Block: 128 queries, 8 warps, each warp owns 16 query rows.
// Inner tile: 64 keys. All fragments via ldmatrix (V via ldmatrix.trans).
// Q/K/V arrive fp16 (Q pre-scaled). Smem pitch 72 halves (144B):
// row-start banks 4r mod 32 bijective over 8 rows -> conflict-free.
// ---------------------------------------------------------------------------
#define AQT 128
#define AKT 64
#define PH  72                       // pitch (halves) for all attn tiles
#define QS_H 0
#define KS_H (AQT * PH)              // 9216
#define VS_H (KS_H + AKT * PH)       // 13824
#define PS_H (VS_H + AKT * PH)       // 18432
#define ATTN_SMEM ((PS_H + AQT * PH) * 2)   // 55296 bytes

__global__ __launch_bounds__(256, 2)
void attn_tc(const __half* __restrict__ Q, const __half* __restrict__ K,
             const __half* __restrict__ V, __half* __restrict__ O)
{
    extern __shared__ uint32_t asmem[];
    __half* smh = (__half*)asmem;

    const int tid  = threadIdx.x;
    const int wid  = tid >> 5;
    const int lane = tid & 31;
    const int g    = lane >> 2;
    const int t    = lane & 3;
    const int bh   = blockIdx.y;
    const int b    = bh >> 4;
    const int h    = bh & 15;
    const int q0   = blockIdx.x * AQT;
    const size_t base = (size_t)b * SEQ * D_MODEL + (size_t)h * DK;

    // load Q tile (fp16, already scaled): 1024 16B-chunks
#pragma unroll
    for (int e = 0; e < 4; e++) {
        int idx = tid + 256 * e;
        int r = idx >> 3, ch = idx & 7;
        ((uint4*)(smh + QS_H + r * PH))[ch] =
            *((const uint4*)(Q + base + (size_t)(q0 + r) * D_MODEL) + ch);
    }

    float m0 = -1e30f, m1 = -1e30f, l0 = 0.f, l1 = 0.f;
    float oacc[8][4];
#pragma unroll
    for (int nt = 0; nt < 8; nt++)
#pragma unroll
        for (int e = 0; e < 4; e++) oacc[nt][e] = 0.f;

    const int qrow = wid * 16;

    // ldmatrix lane addresses
    const uint32_t sb = (uint32_t)__cvta_generic_to_shared(asmem);
    const int lr = lane & 7, sel = lane >> 3;
    const int aro = (sel & 1) * 8 + lr, aco = (sel >> 1) * 8;
    const int bro = (sel >> 1) * 8 + lr, bco = (sel & 1) * 8;
    const uint32_t q_lm = sb + (uint32_t)(QS_H + (qrow + aro) * PH + aco) * 2;
    const uint32_t p_lm = sb + (uint32_t)(PS_H + (qrow + aro) * PH + aco) * 2;
    uint32_t k_lm[4];
#pragma unroll
    for (int p = 0; p < 4; p++)
        k_lm[p] = sb + (uint32_t)(KS_H + (p * 16 + bro) * PH + bco) * 2;
    // V (trans): matrix rows = keys, cols = dims
    const int vro = (sel & 1) * 8 + lr, vco = (sel >> 1) * 8;
    uint32_t v_lm[4];
#pragma unroll
    for (int p = 0; p < 4; p++)
        v_lm[p] = sb + (uint32_t)(VS_H + vro * PH + p * 16 + vco) * 2;

    for (int k0 = 0; k0 < SEQ; k0 += AKT) {
        __syncthreads();
        // load K,V tiles: 512 16B-chunks each
#pragma unroll
        for (int e = 0; e < 2; e++) {
            int idx = tid + 256 * e;
            int r = idx >> 3, ch = idx & 7;
            const size_t grow = base + (size_t)(k0 + r) * D_MODEL;
            ((uint4*)(smh + KS_H + r * PH))[ch] = *((const uint4*)(K + grow) + ch);
            ((uint4*)(smh + VS_H + r * PH))[ch] = *((const uint4*)(V + grow) + ch);
        }
        __syncthreads();

        // ---- S = Q K^T : m16 x n64, k=64 (4 k16 steps) ----
        float sacc[8][4];
#pragma unroll
        for (int nt = 0; nt < 8; nt++)
#pragma unroll
            for (int e = 0; e < 4; e++) sacc[nt][e] = 0.f;

#pragma unroll
        for (int ks = 0; ks < 4; ks++) {
            uint32_t a[4];
            ldm_x4(a, q_lm + ks * 32);
            uint32_t kf[4][4];
#pragma unroll
            for (int p = 0; p < 4; p++)
                ldm_x4(kf[p], k_lm[p] + ks * 32);
#pragma unroll
            for (int nt = 0; nt < 8; nt++)
                mma_f16(sacc[nt], a, &kf[nt >> 1][(nt & 1) * 2]);
        }

        // ---- online softmax (rows qrow+g, qrow+g+8) ----
        float rmax0 = -1e30f, rmax1 = -1e30f;
#pragma unroll
        for (int nt = 0; nt < 8; nt++) {
            rmax0 = fmaxf(rmax0, fmaxf(sacc[nt][0], sacc[nt][1]));
            rmax1 = fmaxf(rmax1, fmaxf(sacc[nt][2], sacc[nt][3]));
        }
        rmax0 = fmaxf(rmax0, __shfl_xor_sync(0xffffffffu, rmax0, 1));
        rmax0 = fmaxf(rmax0, __shfl_xor_sync(0xffffffffu, rmax0, 2));
        rmax1 = fmaxf(rmax1, __shfl_xor_sync(0xffffffffu, rmax1, 1));
        rmax1 = fmaxf(rmax1, __shfl_xor_sync(0xffffffffu, rmax1, 2));

        const float nm0 = fmaxf(m0, rmax0);
        const float nm1 = fmaxf(m1, rmax1);
        const float sc0 = __expf(m0 - nm0);
        const float sc1 = __expf(m1 - nm1);

        float rs0 = 0.f, rs1 = 0.f;
        __half* ps0 = smh + PS_H + (qrow + g) * PH;
        __half* ps1 = smh + PS_H + (qrow + g + 8) * PH;
#pragma unroll
        for (int nt = 0; nt < 8; nt++) {
            float p00 = __expf(sacc[nt][0] - nm0);
            float p01 = __expf(sacc[nt][1] - nm0);
            float p10 = __expf(sacc[nt][2] - nm1);
            float p11 = __expf(sacc[nt][3] - nm1);
            rs0 += p00 + p01;
            rs1 += p10 + p11;
            *(__half2*)(ps0 + nt * 8 + 2 * t) = __floats2half2_rn(p00, p01);
            *(__half2*)(ps1 + nt * 8 + 2 * t) = __floats2half2_rn(p10, p11);
        }
        rs0 += __shfl_xor_sync(0xffffffffu, rs0, 1);
        rs0 += __shfl_xor_sync(0xffffffffu, rs0, 2);
        rs1 += __shfl_xor_sync(0xffffffffu, rs1, 1);
        rs1 += __shfl_xor_sync(0xffffffffu, rs1, 2);

        m0 = nm0; m1 = nm1;
        l0 = l0 * sc0 + rs0;
        l1 = l1 * sc1 + rs1;
#pragma unroll
        for (int nt = 0; nt < 8; nt++) {
            oacc[nt][0] *= sc0; oacc[nt][1] *= sc0;
            oacc[nt][2] *= sc1; oacc[nt][3] *= sc1;
        }

        __syncwarp();   // ps written/read within the warp only

        // ---- O += P V : k=64 keys (4 k16 steps), V via ldmatrix.trans ----
#pragma unroll
        for (int ks = 0; ks < 4; ks++) {
            uint32_t a[4];
            ldm_x4(a, p_lm + ks * 32);
            uint32_t vf[4][4];
#pragma unroll
            for (int p = 0; p < 4; p++)
                ldm_x4_t(vf[p], v_lm[p] + ks * (16 * PH * 2));
#pragma unroll
            for (int nt = 0; nt < 8; nt++)
                mma_f16(oacc[nt], a, &vf[nt >> 1][(nt & 1) * 2]);
        }
    }

    // epilogue: normalize, write fp16
    const float il0 = 1.f / l0;
    const float il1 = 1.f / l1;
#pragma unroll
    for (int nt = 0; nt < 8; nt++) {
        const int c = nt * 8 + 2 * t;
        __half2 u0 = __floats2half2_rn(oacc[nt][0] * il0, oacc[nt][1] * il0);
        __half2 u1 = __floats2half2_rn(oacc[nt][2] * il1, oacc[nt][3] * il1);
        *(__half2*)(O + base + (size_t)(q0 + qrow + g    ) * D_MODEL + c) = u0;
        *(__half2*)(O + base + (size_t)(q0 + qrow + g + 8) * D_MODEL + c) = u1;
    }
}

// ---------------------------------------------------------------------------
// LayerNorm over last dim (1024); optional fp16 copy output.
// ---------------------------------------------------------------------------
__global__ __launch_bounds__(256)
void ln_kernel(const float* __restrict__ X, const float* __restrict__ g,
               const float* __restrict__ b, float* __restrict__ Y,
               __half* __restrict__ Yh)
{
    const int row = blockIdx.x;
    const float* x = X + (size_t)row * D_MODEL;

    float v[4];
    float s = 0.f, s2 = 0.f;
#pragma unroll
    for (int e = 0; e < 4; e++) {
        v[e] = x[threadIdx.x + 256 * e];
        s  += v[e];
        s2 += v[e] * v[e];
    }
#pragma unroll
    for (int off = 16; off; off >>= 1) {
        s  += __shfl_xor_sync(0xffffffffu, s,  off);
        s2 += __shfl_xor_sync(0xffffffffu, s2, off);
    }
    __shared__ float rs[8], rs2[8];
    const int w = threadIdx.x >> 5, lane = threadIdx.x & 31;
    if (lane == 0) { rs[w] = s; rs2[w] = s2; }
    __syncthreads();
    s = 0.f; s2 = 0.f;
#pragma unroll
    for (int i = 0; i < 8; i++) { s += rs[i]; s2 += rs2[i]; }

    const float mean = s * (1.f / D_MODEL);
    const float var  = s2 * (1.f / D_MODEL) - mean * mean;
    const float rstd = rsqrtf(var + 1e-5f);

    float* y = Y + (size_t)row * D_MODEL;
#pragma unroll
    for (int e = 0; e < 4; e++) {
        int c = threadIdx.x + 256 * e;
        float val = (v[e] - mean) * rstd * g[c] + b[c];
        y[c] = val;
        if (Yh) Yh[(size_t)row * D_MODEL + c] = __float2half_rn(val);
    }
}

// ---------------------------------------------------------------------------
// Launch
// ---------------------------------------------------------------------------
extern "C" void kernel_launch(void* const* d_in, const int* in_sizes, int n_in,
                              void* d_out, int out_size)
{
    const float* x     = (const float*)d_in[0];
    const float* wq    = (const float*)d_in[1];
    const float* bq    = (const float*)d_in[2];
    const float* wk    = (const float*)d_in[3];
    const float* bk    = (const float*)d_in[4];
    const float* wv    = (const float*)d_in[5];
    const float* bv    = (const float*)d_in[6];
    const float* wo    = (const float*)d_in[7];
    const float* bo    = (const float*)d_in[8];
    const float* ln1_g = (const float*)d_in[9];
    const float* ln1_b = (const float*)d_in[10];
    const float* ln2_g = (const float*)d_in[11];
    const float* ln2_b = (const float*)d_in[12];
    const float* w1    = (const float*)d_in[13];
    const float* b1    = (const float*)d_in[14];
    const float* w2    = (const float*)d_in[15];
    const float* b2    = (const float*)d_in[16];
    float* out = (float*)d_out;

    float *x1, *tmp;
    __half *qkvH, *attnH, *x1H, *hH, *xH, *wqkvH, *woH, *w1H, *w2H;
    cudaGetSymbolAddress((void**)&qkvH,  g_qkvH);
    cudaGetSymbolAddress((void**)&attnH, g_attnH);
    cudaGetSymbolAddress((void**)&x1,    g_x1);
    cudaGetSymbolAddress((void**)&x1H,   g_x1H);
    cudaGetSymbolAddress((void**)&tmp,   g_tmp);
    cudaGetSymbolAddress((void**)&hH,    g_hH);
    cudaGetSymbolAddress((void**)&xH,    g_xH);
    cudaGetSymbolAddress((void**)&wqkvH, g_wqkvH);
    cudaGetSymbolAddress((void**)&woH,   g_woH);
    cudaGetSymbolAddress((void**)&w1H,   g_w1H);
    cudaGetSymbolAddress((void**)&w2H,   g_w2H);

    cudaFuncSetAttribute(attn_tc, cudaFuncAttributeMaxDynamicSharedMemorySize,
                         ATTN_SMEM);
    cudaFuncSetAttribute(qkv_tc, cudaFuncAttributeMaxDynamicSharedMemorySize,
                         GEMM_SMEM);
    cudaFuncSetAttribute(gemm_tc<2, 0>, cudaFuncAttributeMaxDynamicSharedMemorySize,
                         GEMM_SMEM);
    cudaFuncSetAttribute(gemm_tc<1, 1>, cudaFuncAttributeMaxDynamicSharedMemorySize,
                         GEMM_SMEM);

    const dim3 blk(256);
    const dim3 tblk(32, 8);

    // pre-pass: convert x; transpose+convert weights to fp16
    cvt_f16_vec<<<MTOT * D_MODEL / 4 / 256, blk>>>(x, xH);
    transp_qkvo<<<dim3(32, 32, 4), tblk>>>(wq, wk, wv, wo, wqkvH, woH);
    transp_gen<<<dim3(DFF / 32, D_MODEL / 32), tblk>>>(w1, w1H, D_MODEL, DFF);
    transp_gen<<<dim3(D_MODEL / 32, DFF / 32), tblk>>>(w2, w2H, DFF, D_MODEL);

    // QKV (fused, z = 0/1/2), Q pre-scaled by 0.125
    qkv_tc<<<dim3(D_MODEL / 128, MTOT / 128, 3), blk, GEMM_SMEM>>>(
        xH, wqkvH, bq, bk, bv, qkvH);

    // attention
    attn_tc<<<dim3(SEQ / AQT, BATCH * NH), blk, ATTN_SMEM>>>(
        qkvH, qkvH + (size_t)MTOT * D_MODEL, qkvH + (size_t)2 * MTOT * D_MODEL,
        attnH);

    // O-proj + residual -> LN1
    gemm_tc<2, 0><<<dim3(D_MODEL / 128, MTOT / 128), blk, GEMM_SMEM>>>(
        attnH, woH, bo, x, tmp, D_MODEL, D_MODEL);
    ln_kernel<<<MTOT, blk>>>(tmp, ln1_g, ln1_b, x1, x1H);

    // FFN
    gemm_tc<1, 1><<<dim3(DFF / 128, MTOT / 128), blk, GEMM_SMEM>>>(
        x1H, w1H, b1, nullptr, hH, DFF, D_MODEL);
    gemm_tc<2, 0><<<dim3(D_MODEL / 128, MTOT / 128), blk, GEMM_SMEM>>>(
        hH, w2H, b2, x1, tmp, D_MODEL, DFF);
    ln_kernel<<<MTOT, blk>>>(tmp, ln2_g, ln2_b, out, nullptr);
}

// round 9
// speedup vs baseline: 1.8692x; 1.0051x over previous
#include <cuda_runtime.h>
#include <cuda_fp16.h>
#include <cstdint>
#include <cstddef>

// Problem dims (fixed by the reference)
#define D_MODEL 1024
#define SEQ     2048
#define BATCH   2
#define NH      16
#define DK      64
#define DFF     4096
#define MTOT    (BATCH * SEQ)   // 4096 rows

// ---------------------------------------------------------------------------
// Scratch (no allocation allowed -> __device__ globals)
// ---------------------------------------------------------------------------
__device__ __half g_qkvH [3 * MTOT * D_MODEL];  // q|k|v, fp16 (q pre-scaled by 1/8)
__device__ __half g_attnH[MTOT * D_MODEL];      // attn out, fp16
__device__ float  g_x1   [MTOT * D_MODEL];
__device__ __half g_x1H  [MTOT * D_MODEL];
__device__ float  g_tmp  [MTOT * D_MODEL];
__device__ __half g_hH   [MTOT * DFF];          // relu(ffn1), fp16
__device__ __half g_xH   [MTOT * D_MODEL];      // x, fp16
__device__ __half g_wqkvH[3 * D_MODEL * D_MODEL];   // [K][N] (no transpose)
__device__ __half g_woH  [D_MODEL * D_MODEL];
__device__ __half g_w1H  [D_MODEL * DFF];
__device__ __half g_w2H  [DFF * D_MODEL];

// ---------------------------------------------------------------------------
// helpers
// ---------------------------------------------------------------------------
__device__ __forceinline__ void mma_f16(float c[4], const uint32_t a[4],
                                        const uint32_t b[2]) {
    asm("mma.sync.aligned.m16n8k16.row.col.f32.f16.f16.f32 "
        "{%0,%1,%2,%3}, {%4,%5,%6,%7}, {%8,%9}, {%0,%1,%2,%3};"
        : "+f"(c[0]), "+f"(c[1]), "+f"(c[2]), "+f"(c[3])
        : "r"(a[0]), "r"(a[1]), "r"(a[2]), "r"(a[3]), "r"(b[0]), "r"(b[1]));
}

__device__ __forceinline__ void ldm_x4(uint32_t r[4], uint32_t addr) {
    asm volatile("ldmatrix.sync.aligned.m8n8.x4.shared.b16 {%0,%1,%2,%3}, [%4];"
                 : "=r"(r[0]), "=r"(r[1]), "=r"(r[2]), "=r"(r[3]) : "r"(addr));
}
__device__ __forceinline__ void ldm_x4_t(uint32_t r[4], uint32_t addr) {
    asm volatile("ldmatrix.sync.aligned.m8n8.x4.trans.shared.b16 {%0,%1,%2,%3}, [%4];"
                 : "=r"(r[0]), "=r"(r[1]), "=r"(r[2]), "=r"(r[3]) : "r"(addr));
}

__device__ __forceinline__ void cp16(uint32_t saddr, const void* gptr) {
    asm volatile("cp.async.cg.shared.global [%0], [%1], 16;"
                 :: "r"(saddr), "l"(gptr));
}
__device__ __forceinline__ void cp_commit() { asm volatile("cp.async.commit_group;"); }
__device__ __forceinline__ void cp_wait2()  { asm volatile("cp.async.wait_group 2;"); }
__device__ __forceinline__ void cp_wait1()  { asm volatile("cp.async.wait_group 1;"); }

// ---------------------------------------------------------------------------
// fp16 tensor-core GEMM. A: [M][K] fp16 row-major. W: [K][N] fp16 row-major
// (NO pre-transpose; B fragments via ldmatrix.trans — the R8-attention-PV-
// proven lane map). Block 128x128 x K32, 256 threads = 8 warps (2M x 4N),
// warp tile 64x32, mma m16n8k16. A pitch 40 halves, B pitch 136 halves
// (both conflict-free per ldmatrix 8-address phase). cp.async 4 stages.
// EPI: 0=bias, 1=bias+relu, 2=bias+res. OUTH: write fp16. oscale after bias.
// ---------------------------------------------------------------------------
#define GPA 40                       // A pitch (halves)
#define GPB 136                      // B pitch (halves)
#define ATILE_B (128 * GPA * 2)      // 10240
#define BTILE_B (32 * GPB * 2)       // 8704
#define STG_B   (ATILE_B + BTILE_B)  // 18944
#define GSTAGES 4
#define GEMM_SMEM (GSTAGES * STG_B)  // 75776

template <int EPI, int OUTH>
__device__ __forceinline__ void gemm_body(
    const __half* __restrict__ A, const __half* __restrict__ W,
    const float* __restrict__ bias, const float* __restrict__ res,
    void* __restrict__ Cv, int N, int K, int bm, int bn, float oscale)
{
    extern __shared__ uint32_t gsm[];

    const int tid  = threadIdx.x;
    const int wid  = tid >> 5;
    const int lane = tid & 31;
    const int g    = lane >> 2;
    const int t    = lane & 3;
    const int wm   = (wid & 1) * 64;
    const int wn   = (wid >> 1) * 32;

    float acc[4][4][4];
#pragma unroll
    for (int i = 0; i < 4; i++)
#pragma unroll
        for (int j = 0; j < 4; j++)
#pragma unroll
            for (int e = 0; e < 4; e++) acc[i][j][e] = 0.f;

    // cp.async A: 128 rows x 4 chunks -> 2 per thread
    const int ar0 = tid >> 2,         ac0 = tid & 3;
    const int ar1 = (tid + 256) >> 2, ac1 = (tid + 256) & 3;
    // cp.async B: 32 rows x 16 chunks -> 2 per thread
    const int br = tid >> 4, bch = tid & 15;

    const uint32_t sbase = (uint32_t)__cvta_generic_to_shared(gsm);
    const uint32_t aS0 = sbase + (uint32_t)(ar0 * GPA + ac0 * 8) * 2;
    const uint32_t aS1 = sbase + (uint32_t)(ar1 * GPA + ac1 * 8) * 2;
    const uint32_t bSc = sbase + ATILE_B + (uint32_t)(br * GPB + bch * 8) * 2;
    const __half* aG0 = A + (size_t)(bm + ar0) * K + ac0 * 8;
    const __half* aG1 = A + (size_t)(bm + ar1) * K + ac1 * 8;
    const __half* bGc = W + (size_t)br * N + bn + bch * 8;

#define GI(kt)                                                                 \
    {                                                                          \
        const uint32_t so_ = ((kt) & 3) * STG_B;                               \
        const int k0_ = (kt) * 32;                                             \
        cp16(aS0 + so_, aG0 + k0_);                                            \
        cp16(aS1 + so_, aG1 + k0_);                                            \
        cp16(bSc + so_, bGc + (size_t)k0_ * N);                                \
        cp16(bSc + so_ + 16 * GPB * 2, bGc + (size_t)(k0_ + 16) * N);          \
    }

    // ldmatrix lane maps
    const int lr = lane & 7, sel = lane >> 3;
    const int aro = (sel & 1) * 8 + lr, aco = (sel >> 1) * 8;
    uint32_t a_lm[4];
#pragma unroll
    for (int mt = 0; mt < 4; mt++)
        a_lm[mt] = sbase + (uint32_t)((wm + mt * 16 + aro) * GPA + aco) * 2;
    // B trans map (identical to R8 attention V): row = k, col = n
    const int vro = (sel & 1) * 8 + lr, vco = (sel >> 1) * 8;
    uint32_t b_lm[2];
#pragma unroll
    for (int p = 0; p < 2; p++)
        b_lm[p] = sbase + ATILE_B +
                  (uint32_t)(vro * GPB + wn + p * 16 + vco) * 2;

    const int nk = K >> 5;
#pragma unroll
    for (int s = 0; s < GSTAGES - 1; s++) { GI(s) cp_commit(); }

    for (int kt = 0; kt < nk; kt++) {
        cp_wait2();
        __syncthreads();
        if (kt + GSTAGES - 1 < nk) { GI(kt + GSTAGES - 1) }
        cp_commit();

        const uint32_t so = (kt & 3) * STG_B;
#pragma unroll
        for (int ks = 0; ks < 2; ks++) {
            uint32_t af[4][4];
#pragma unroll
            for (int mt = 0; mt < 4; mt++)
                ldm_x4(af[mt], a_lm[mt] + so + ks * 32);
            uint32_t bf[2][4];
            ldm_x4_t(bf[0], b_lm[0] + so + ks * (16 * GPB * 2));
            ldm_x4_t(bf[1], b_lm[1] + so + ks * (16 * GPB * 2));
#pragma unroll
            for (int mt = 0; mt < 4; mt++)
#pragma unroll
                for (int nt = 0; nt < 4; nt++)
                    mma_f16(acc[mt][nt], af[mt], &bf[nt >> 1][(nt & 1) * 2]);
        }
    }
#undef GI

    // epilogue
#pragma unroll
    for (int mt = 0; mt < 4; mt++) {
        const int r = bm + wm + mt * 16 + g;
#pragma unroll
        for (int nt = 0; nt < 4; nt++) {
            const int c = bn + wn + nt * 8 + 2 * t;
            const float2 bb = *(const float2*)(bias + c);
            float2 v0, v1;
            v0.x = (acc[mt][nt][0] + bb.x) * oscale;
            v0.y = (acc[mt][nt][1] + bb.y) * oscale;
            v1.x = (acc[mt][nt][2] + bb.x) * oscale;
            v1.y = (acc[mt][nt][3] + bb.y) * oscale;
            if (EPI == 1) {
                v0.x = fmaxf(v0.x, 0.f); v0.y = fmaxf(v0.y, 0.f);
                v1.x = fmaxf(v1.x, 0.f); v1.y = fmaxf(v1.y, 0.f);
            }
            if (EPI == 2) {
                const float2 q0r = *(const float2*)(res + (size_t)r * N + c);
                const float2 q1r = *(const float2*)(res + (size_t)(r + 8) * N + c);
                v0.x += q0r.x; v0.y += q0r.y;
                v1.x += q1r.x; v1.y += q1r.y;
            }
            if (OUTH) {
                __half* C = (__half*)Cv;
                *(__half2*)(C + (size_t)r * N + c)       = __floats2half2_rn(v0.x, v0.y);
                *(__half2*)(C + (size_t)(r + 8) * N + c) = __floats2half2_rn(v1.x, v1.y);
            } else {
                float* C = (float*)Cv;
                *(float2*)(C + (size_t)r * N + c)       = v0;
                *(float2*)(C + (size_t)(r + 8) * N + c) = v1;
            }
        }
    }
}

template <int EPI, int OUTH>
__global__ __launch_bounds__(256, 2)
void gemm_tc(const __half* __restrict__ A, const __half* __restrict__ W,
             const float* __restrict__ bias, const float* __restrict__ res,
             void* __restrict__ C, int N, int K)
{
    gemm_body<EPI, OUTH>(A, W, bias, res, C, N, K,
                         blockIdx.y * 128, blockIdx.x * 128, 1.f);
}

// fused QKV: gridDim.z = 3; Q output pre-scaled by 1/sqrt(DK) = 0.125
__global__ __launch_bounds__(256, 2)
void qkv_tc(const __half* __restrict__ xH, const __half* __restrict__ wqkvH,
            const float* __restrict__ bq, const float* __restrict__ bk,
            const float* __restrict__ bv, __half* __restrict__ qkvH)
{
    const int z = blockIdx.z;
    const float* bias = (z == 0) ? bq : (z == 1) ? bk : bv;
    gemm_body<0, 1>(xH, wqkvH + (size_t)z * D_MODEL * D_MODEL, bias, nullptr,
                    qkvH + (size_t)z * MTOT * D_MODEL, D_MODEL, D_MODEL,
                    blockIdx.y * 128, blockIdx.x * 128,
                    (z == 0) ? 0.125f : 1.f);
}

// ---------------------------------------------------------------------------
// Pre-pass: pure fp32 -> fp16 element-wise convert (no transposes).
// ---------------------------------------------------------------------------
__global__ void cvt_f16_vec(const float* __restrict__ X, __half* __restrict__ Y)
{
    const int i = blockIdx.x * blockDim.x + threadIdx.x;
    float4 v = ((const float4*)X)[i];
    __half2 h0 = __floats2half2_rn(v.x, v.y);
    __half2 h1 = __floats2half2_rn(v.z, v.w);
    uint2 u;
    u.x = *(uint32_t*)&h0;
    u.y = *(uint32_t*)&h1;
    ((uint2*)Y)[i] = u;
}

// ---------------------------------------------------------------------------
// fp16 flash attention, cp.async 3-stage K/V pipeline (GEMM-proven rotation:
// always-commit + wait_group 1, single __syncthreads per tile, issue slot
// (kt+2)%3 = slot compute vacated last iteration).
// Block: 128 queries, 8 warps x 16 query rows; 64-key inner tile.
// All fragments via ldmatrix (V via .trans). Pitch 72 halves everywhere.
// ---------------------------------------------------------------------------
#define AQT 128
#define AKT 64
#define PH  72
#define QH  (AQT * PH)               // 9216 halves
#define KVST (2 * AKT * PH)          // 9216 halves per stage (K + V)
#define PS_H (QH + 3 * KVST)         // 36864
#define ATTN_SMEM ((PS_H + AQT * PH) * 2)   // 92160 bytes

__global__ __launch_bounds__(256, 2)
void attn_tc(const __half* __restrict__ Q, const __half* __restrict__ K,
             const __half* __restrict__ V, __half* __restrict__ O)
{
    extern __shared__ uint32_t asmem[];
    __half* smh = (__half*)asmem;

    const int tid  = threadIdx.x;
    const int wid  = tid >> 5;
    const int lane = tid & 31;
    const int g    = lane >> 2;
    const int t    = lane & 3;
    const int bh   = blockIdx.y;
    const int b    = bh >> 4;
    const int h    = bh & 15;
    const int q0   = blockIdx.x * AQT;
    const size_t base = (size_t)b * SEQ * D_MODEL + (size_t)h * DK;

    // load Q tile (fp16, pre-scaled): 1024 16B-chunks
#pragma unroll
    for (int e = 0; e < 4; e++) {
        int idx = tid + 256 * e;
        int r = idx >> 3, ch = idx & 7;
        ((uint4*)(smh + r * PH))[ch] =
            *((const uint4*)(Q + base + (size_t)(q0 + r) * D_MODEL) + ch);
    }

    float m0 = -1e30f, m1 = -1e30f, l0 = 0.f, l1 = 0.f;
    float oacc[8][4];
#pragma unroll
    for (int nt = 0; nt < 8; nt++)
#pragma unroll
        for (int e = 0; e < 4; e++) oacc[nt][e] = 0.f;

    const int qrow = wid * 16;

    // cp.async K/V stage loader: per tile 64 rows x 8 chunks; thread -> 2 rows
    const int kvr = tid >> 3, kvc = tid & 7;
    const uint32_t sb = (uint32_t)__cvta_generic_to_shared(asmem);
    const uint32_t kS = sb + (uint32_t)QH * 2 + (uint32_t)(kvr * PH + kvc * 8) * 2;

#define CPKV(slot, kt_)                                                        \
    {                                                                          \
        const uint32_t so_ = (uint32_t)(slot) * (KVST * 2);                    \
        const size_t gr0 = base + (size_t)((kt_) * AKT + kvr) * D_MODEL;       \
        const size_t gr1 = gr0 + (size_t)32 * D_MODEL;                         \
        cp16(kS + so_, K + gr0 + kvc * 8);                                     \
        cp16(kS + so_ + 32 * PH * 2, K + gr1 + kvc * 8);                       \
        cp16(kS + so_ + AKT * PH * 2, V + gr0 + kvc * 8);                      \
        cp16(kS + so_ + AKT * PH * 2 + 32 * PH * 2, V + gr1 + kvc * 8);        \
    }

    // ldmatrix lane maps
    const int lr = lane & 7, sel = lane >> 3;
    const int aro = (sel & 1) * 8 + lr, aco = (sel >> 1) * 8;
    const int bro = (sel >> 1) * 8 + lr, bco = (sel & 1) * 8;
    const int vro = (sel & 1) * 8 + lr, vco = (sel >> 1) * 8;
    const uint32_t q_lm = sb + (uint32_t)((qrow + aro) * PH + aco) * 2;
    const uint32_t p_lm = sb + (uint32_t)(PS_H + (qrow + aro) * PH + aco) * 2;
    uint32_t k_lm[4], v_lm[4];
#pragma unroll
    for (int p = 0; p < 4; p++) {
        k_lm[p] = (uint32_t)((p * 16 + bro) * PH + bco) * 2;          // rel K tile
        v_lm[p] = (uint32_t)(vro * PH + p * 16 + vco) * 2;            // rel V tile
    }

    const int nk = SEQ / AKT;   // 32
    CPKV(0, 0) cp_commit();
    CPKV(1, 1) cp_commit();

    int csl = 0, isl = 2;
    for (int kt = 0; kt < nk; kt++) {
        cp_wait1();
        __syncthreads();
        if (kt + 2 < nk) { CPKV(isl, kt + 2) isl = (isl == 2) ? 0 : isl + 1; }
        cp_commit();

        const uint32_t kb = (uint32_t)QH * 2 + (uint32_t)csl * (KVST * 2);
        const uint32_t vb = kb + (uint32_t)(AKT * PH) * 2;

        // ---- S = Q K^T : 4 k16 steps ----
        float sacc[8][4];
#pragma unroll
        for (int nt = 0; nt < 8; nt++)
#pragma unroll
            for (int e = 0; e < 4; e++) sacc[nt][e] = 0.f;

#pragma unroll
        for (int ks = 0; ks < 4; ks++) {
            uint32_t a[4];
            ldm_x4(a, q_lm + ks * 32);
            uint32_t kf[4][4];
#pragma unroll
            for (int p = 0; p < 4; p++)
                ldm_x4(kf[p], sb + kb + k_lm[p] + ks * 32);
#pragma unroll
            for (int nt = 0; nt < 8; nt++)
                mma_f16(sacc[nt], a, &kf[nt >> 1][(nt & 1) * 2]);
        }

        // ---- online softmax ----
        float rmax0 = -1e30f, rmax1 = -1e30f;
#pragma unroll
        for (int nt = 0; nt < 8; nt++) {
            rmax0 = fmaxf(rmax0, fmaxf(sacc[nt][0], sacc[nt][1]));
            rmax1 = fmaxf(rmax1, fmaxf(sacc[nt][2], sacc[nt][3]));
        }
        rmax0 = fmaxf(rmax0, __shfl_xor_sync(0xffffffffu, rmax0, 1));
        rmax0 = fmaxf(rmax0, __shfl_xor_sync(0xffffffffu, rmax0, 2));
        rmax1 = fmaxf(rmax1, __shfl_xor_sync(0xffffffffu, rmax1, 1));
        rmax1 = fmaxf(rmax1, __shfl_xor_sync(0xffffffffu, rmax1, 2));

        const float nm0 = fmaxf(m0, rmax0);
        const float nm1 = fmaxf(m1, rmax1);
        const float sc0 = __expf(m0 - nm0);
        const float sc1 = __expf(m1 - nm1);

        float rs0 = 0.f, rs1 = 0.f;
        __half* ps0 = smh + PS_H + (qrow + g) * PH;
        __half* ps1 = smh + PS_H + (qrow + g + 8) * PH;
#pragma unroll
        for (int nt = 0; nt < 8; nt++) {
            float p00 = __expf(sacc[nt][0] - nm0);
            float p01 = __expf(sacc[nt][1] - nm0);
            float p10 = __expf(sacc[nt][2] - nm1);
            float p11 = __expf(sacc[nt][3] - nm1);
            rs0 += p00 + p01;
            rs1 += p10 + p11;
            *(__half2*)(ps0 + nt * 8 + 2 * t) = __floats2half2_rn(p00, p01);
            *(__half2*)(ps1 + nt * 8 + 2 * t) = __floats2half2_rn(p10, p11);
        }
        rs0 += __shfl_xor_sync(0xffffffffu, rs0, 1);
        rs0 += __shfl_xor_sync(0xffffffffu, rs0, 2);
        rs1 += __shfl_xor_sync(0xffffffffu, rs1, 1);
        rs1 += __shfl_xor_sync(0xffffffffu, rs1, 2);

        m0 = nm0; m1 = nm1;
        l0 = l0 * sc0 + rs0;
        l1 = l1 * sc1 + rs1;
#pragma unroll
        for (int nt = 0; nt < 8; nt++) {
            oacc[nt][0] *= sc0; oacc[nt][1] *= sc0;
            oacc[nt][2] *= sc1; oacc[nt][3] *= sc1;
        }

        __syncwarp();   // ps written/read within the warp only

        // ---- O += P V : V via ldmatrix.trans ----
#pragma unroll
        for (int ks = 0; ks < 4; ks++) {
            uint32_t a[4];
            ldm_x4(a, p_lm + ks * 32);
            uint32_t vf[4][4];
#pragma unroll
            for (int p = 0; p < 4; p++)
                ldm_x4_t(vf[p], sb + vb + v_lm[p] + ks * (16 * PH * 2));
#pragma unroll
            for (int nt = 0; nt < 8; nt++)
                mma_f16(oacc[nt], a, &vf[nt >> 1][(nt & 1) * 2]);
        }

        csl = (csl == 2) ? 0 : csl + 1;
    }
#undef CPKV

    // epilogue: normalize, write fp16
    const float il0 = 1.f / l0;
    const float il1 = 1.f / l1;
#pragma unroll
    for (int nt = 0; nt < 8; nt++) {
        const int c = nt * 8 + 2 * t;
        __half2 u0 = __floats2half2_rn(oacc[nt][0] * il0, oacc[nt][1] * il0);
        __half2 u1 = __floats2half2_rn(oacc[nt][2] * il1, oacc[nt][3] * il1);
        *(__half2*)(O + base + (size_t)(q0 + qrow + g    ) * D_MODEL + c) = u0;
        *(__half2*)(O + base + (size_t)(q0 + qrow + g + 8) * D_MODEL + c) = u1;
    }
}

// ---------------------------------------------------------------------------
// LayerNorm over last dim (1024), float4 path; optional fp16 copy output.
// ---------------------------------------------------------------------------
__global__ __launch_bounds__(256)
void ln_kernel(const float* __restrict__ X, const float* __restrict__ g,
               const float* __restrict__ b, float* __restrict__ Y,
               __half* __restrict__ Yh)
{
    const int row = blockIdx.x;
    const int tid = threadIdx.x;
    const float4 v = *((const float4*)(X + (size_t)row * D_MODEL) + tid);

    float s  = v.x + v.y + v.z + v.w;
    float s2 = v.x * v.x + v.y * v.y + v.z * v.z + v.w * v.w;
#pragma unroll
    for (int off = 16; off; off >>= 1) {
        s  += __shfl_xor_sync(0xffffffffu, s,  off);
        s2 += __shfl_xor_sync(0xffffffffu, s2, off);
    }
    __shared__ float rs[8], rs2[8];
    const int w = tid >> 5, lane = tid & 31;
    if (lane == 0) { rs[w] = s; rs2[w] = s2; }
    __syncthreads();
    s = 0.f; s2 = 0.f;
#pragma unroll
    for (int i = 0; i < 8; i++) { s += rs[i]; s2 += rs2[i]; }

    const float mean = s * (1.f / D_MODEL);
    const float var  = s2 * (1.f / D_MODEL) - mean * mean;
    const float rstd = rsqrtf(var + 1e-5f);

    const float4 gg = *((const float4*)g + tid);
    const float4 bb = *((const float4*)b + tid);
    float4 y;
    y.x = (v.x - mean) * rstd * gg.x + bb.x;
    y.y = (v.y - mean) * rstd * gg.y + bb.y;
    y.z = (v.z - mean) * rstd * gg.z + bb.z;
    y.w = (v.w - mean) * rstd * gg.w + bb.w;
    *((float4*)(Y + (size_t)row * D_MODEL) + tid) = y;
    if (Yh) {
        __half2 h0 = __floats2half2_rn(y.x, y.y);
        __half2 h1 = __floats2half2_rn(y.z, y.w);
        uint2 u;
        u.x = *(uint32_t*)&h0;
        u.y = *(uint32_t*)&h1;
        *((uint2*)(Yh + (size_t)row * D_MODEL) + tid) = u;
    }
}

// ---------------------------------------------------------------------------
// Launch
// ---------------------------------------------------------------------------
extern "C" void kernel_launch(void* const* d_in, const int* in_sizes, int n_in,
                              void* d_out, int out_size)
{
    const float* x     = (const float*)d_in[0];
    const float* wq    = (const float*)d_in[1];
    const float* bq    = (const float*)d_in[2];
    const float* wk    = (const float*)d_in[3];
    const float* bk    = (const float*)d_in[4];
    const float* wv    = (const float*)d_in[5];
    const float* bv    = (const float*)d_in[6];
    const float* wo    = (const float*)d_in[7];
    const float* bo    = (const float*)d_in[8];
    const float* ln1_g = (const float*)d_in[9];
    const float* ln1_b = (const float*)d_in[10];
    const float* ln2_g = (const float*)d_in[11];
    const float* ln2_b = (const float*)d_in[12];
    const float* w1    = (const float*)d_in[13];
    const float* b1    = (const float*)d_in[14];
    const float* w2    = (const float*)d_in[15];
    const float* b2    = (const float*)d_in[16];
    float* out = (float*)d_out;

    float *x1, *tmp;
    __half *qkvH, *attnH, *x1H, *hH, *xH, *wqkvH, *woH, *w1H, *w2H;
    cudaGetSymbolAddress((void**)&qkvH,  g_qkvH);
    cudaGetSymbolAddress((void**)&attnH, g_attnH);
    cudaGetSymbolAddress((void**)&x1,    g_x1);
    cudaGetSymbolAddress((void**)&x1H,   g_x1H);
    cudaGetSymbolAddress((void**)&tmp,   g_tmp);
    cudaGetSymbolAddress((void**)&hH,    g_hH);
    cudaGetSymbolAddress((void**)&xH,    g_xH);
    cudaGetSymbolAddress((void**)&wqkvH, g_wqkvH);
    cudaGetSymbolAddress((void**)&woH,   g_woH);
    cudaGetSymbolAddress((void**)&w1H,   g_w1H);
    cudaGetSymbolAddress((void**)&w2H,   g_w2H);

    cudaFuncSetAttribute(attn_tc, cudaFuncAttributeMaxDynamicSharedMemorySize,
                         ATTN_SMEM);
    cudaFuncSetAttribute(qkv_tc, cudaFuncAttributeMaxDynamicSharedMemorySize,
                         GEMM_SMEM);
    cudaFuncSetAttribute(gemm_tc<2, 0>, cudaFuncAttributeMaxDynamicSharedMemorySize,
                         GEMM_SMEM);
    cudaFuncSetAttribute(gemm_tc<1, 1>, cudaFuncAttributeMaxDynamicSharedMemorySize,
                         GEMM_SMEM);

    const dim3 blk(256);
    const int DD = D_MODEL * D_MODEL;

    // pre-pass: fp32 -> fp16 converts (no transposes)
    cvt_f16_vec<<<MTOT * D_MODEL / 1024, blk>>>(x, xH);
    cvt_f16_vec<<<DD / 1024, blk>>>(wq, wqkvH);
    cvt_f16_vec<<<DD / 1024, blk>>>(wk, wqkvH + DD);
    cvt_f16_vec<<<DD / 1024, blk>>>(wv, wqkvH + 2 * DD);
    cvt_f16_vec<<<DD / 1024, blk>>>(wo, woH);
    cvt_f16_vec<<<D_MODEL * DFF / 1024, blk>>>(w1, w1H);
    cvt_f16_vec<<<D_MODEL * DFF / 1024, blk>>>(w2, w2H);

    // QKV (fused, z = 0/1/2), Q pre-scaled by 0.125
    qkv_tc<<<dim3(D_MODEL / 128, MTOT / 128, 3), blk, GEMM_SMEM>>>(
        xH, wqkvH, bq, bk, bv, qkvH);

    // attention
    attn_tc<<<dim3(SEQ / AQT, BATCH * NH), blk, ATTN_SMEM>>>(
        qkvH, qkvH + (size_t)MTOT * D_MODEL, qkvH + (size_t)2 * MTOT * D_MODEL,
        attnH);

    // O-proj + residual -> LN1
    gemm_tc<2, 0><<<dim3(D_MODEL / 128, MTOT / 128), blk, GEMM_SMEM>>>(
        attnH, woH, bo, x, tmp, D_MODEL, D_MODEL);
    ln_kernel<<<MTOT, blk>>>(tmp, ln1_g, ln1_b, x1, x1H);

    // FFN
    gemm_tc<1, 1><<<dim3(DFF / 128, MTOT / 128), blk, GEMM_SMEM>>>(
        x1H, w1H, b1, nullptr, hH, DFF, D_MODEL);
    gemm_tc<2, 0><<<dim3(D_MODEL / 128, MTOT / 128), blk, GEMM_SMEM>>>(
        hH, w2H, b2, x1, tmp, D_MODEL, DFF);
    ln_kernel<<<MTOT, blk>>>(tmp, ln2_g, ln2_b, out, nullptr);
}

// round 10
// speedup vs baseline: 1.9260x; 1.0304x over previous
#include <cuda_runtime.h>
#include <cuda_fp16.h>
#include <cstdint>
#include <cstddef>

// Problem dims (fixed by the reference)
#define D_MODEL 1024
#define SEQ     2048
#define BATCH   2
#define NH      16
#define DK      64
#define DFF     4096
#define MTOT    (BATCH * SEQ)   // 4096 rows

// ---------------------------------------------------------------------------
// Scratch (no allocation allowed -> __device__ globals)
// ---------------------------------------------------------------------------
__device__ __half g_qkvH [3 * MTOT * D_MODEL];  // q|k|v, fp16 (q pre-scaled by 1/8)
__device__ __half g_attnH[MTOT * D_MODEL];      // attn out, fp16
__device__ float  g_x1   [MTOT * D_MODEL];
__device__ __half g_x1H  [MTOT * D_MODEL];
__device__ float  g_tmp  [MTOT * D_MODEL];
__device__ __half g_hH   [MTOT * DFF];          // relu(ffn1), fp16
__device__ __half g_xH   [MTOT * D_MODEL];      // x, fp16
__device__ __half g_wqkvH[3 * D_MODEL * D_MODEL];   // [K][N] (no transpose)
__device__ __half g_woH  [D_MODEL * D_MODEL];
__device__ __half g_w1H  [D_MODEL * DFF];
__device__ __half g_w2H  [DFF * D_MODEL];

// ---------------------------------------------------------------------------
// helpers
// ---------------------------------------------------------------------------
__device__ __forceinline__ void mma_f16(float c[4], const uint32_t a[4],
                                        const uint32_t b[2]) {
    asm("mma.sync.aligned.m16n8k16.row.col.f32.f16.f16.f32 "
        "{%0,%1,%2,%3}, {%4,%5,%6,%7}, {%8,%9}, {%0,%1,%2,%3};"
        : "+f"(c[0]), "+f"(c[1]), "+f"(c[2]), "+f"(c[3])
        : "r"(a[0]), "r"(a[1]), "r"(a[2]), "r"(a[3]), "r"(b[0]), "r"(b[1]));
}

__device__ __forceinline__ void ldm_x4(uint32_t r[4], uint32_t addr) {
    asm volatile("ldmatrix.sync.aligned.m8n8.x4.shared.b16 {%0,%1,%2,%3}, [%4];"
                 : "=r"(r[0]), "=r"(r[1]), "=r"(r[2]), "=r"(r[3]) : "r"(addr));
}
__device__ __forceinline__ void ldm_x4_t(uint32_t r[4], uint32_t addr) {
    asm volatile("ldmatrix.sync.aligned.m8n8.x4.trans.shared.b16 {%0,%1,%2,%3}, [%4];"
                 : "=r"(r[0]), "=r"(r[1]), "=r"(r[2]), "=r"(r[3]) : "r"(addr));
}

__device__ __forceinline__ void cp16(uint32_t saddr, const void* gptr) {
    asm volatile("cp.async.cg.shared.global [%0], [%1], 16;"
                 :: "r"(saddr), "l"(gptr));
}
__device__ __forceinline__ void cp_commit() { asm volatile("cp.async.commit_group;"); }
__device__ __forceinline__ void cp_wait1()  { asm volatile("cp.async.wait_group 1;"); }

// ---------------------------------------------------------------------------
// fp16 tensor-core GEMM. A: [M][K] fp16 row-major. W: [K][N] fp16 row-major.
// Block 128x128 x K64, 256 threads = 8 warps (2M x 4N), warp tile 64x32,
// mma m16n8k16, A frags ldmatrix / B frags ldmatrix.trans (R8/R9-proven maps).
// A pitch 72 halves, B pitch 136 halves (both conflict-free: row-start banks
// 4r mod 32 bijective over 8 rows). cp.async 3 stages, always-commit +
// wait_group 1 rotation (R9-attention-proven).
// EPI: 0=bias, 1=bias+relu, 2=bias+res. OUTH: write fp16. oscale after bias.
// ---------------------------------------------------------------------------
#define KTILE 64
#define GPA 72                       // A pitch (halves)
#define GPB 136                      // B pitch (halves)
#define ATILE_B (128 * GPA * 2)      // 18432
#define BTILE_B (KTILE * GPB * 2)    // 17408
#define STG_B   (ATILE_B + BTILE_B)  // 35840
#define GEMM_SMEM (3 * STG_B)        // 107520

template <int EPI, int OUTH>
__device__ __forceinline__ void gemm_body(
    const __half* __restrict__ A, const __half* __restrict__ W,
    const float* __restrict__ bias, const float* __restrict__ res,
    void* __restrict__ Cv, int N, int K, int bm, int bn, float oscale)
{
    extern __shared__ uint32_t gsm[];

    const int tid  = threadIdx.x;
    const int wid  = tid >> 5;
    const int lane = tid & 31;
    const int g    = lane >> 2;
    const int t    = lane & 3;
    const int wm   = (wid & 1) * 64;
    const int wn   = (wid >> 1) * 32;

    float acc[4][4][4];
#pragma unroll
    for (int i = 0; i < 4; i++)
#pragma unroll
        for (int j = 0; j < 4; j++)
#pragma unroll
            for (int e = 0; e < 4; e++) acc[i][j][e] = 0.f;

    const uint32_t sbase = (uint32_t)__cvta_generic_to_shared(gsm);

    // cp.async per-thread chunk assignment:
    // A tile: 128 rows x 8 chunks (16B) = 1024 -> 4 per thread
    // B tile: 64 rows x 16 chunks       = 1024 -> 4 per thread
#define GI(slot, kt_)                                                          \
    {                                                                          \
        const uint32_t so_ = (uint32_t)(slot) * STG_B;                         \
        const int k0_ = (kt_) * KTILE;                                         \
        _Pragma("unroll")                                                      \
        for (int i = 0; i < 4; i++) {                                          \
            const int idx = tid + 256 * i;                                     \
            const int ar = idx >> 3, ac = idx & 7;                             \
            cp16(sbase + so_ + (uint32_t)(ar * GPA + ac * 8) * 2,              \
                 A + (size_t)(bm + ar) * K + k0_ + ac * 8);                    \
        }                                                                      \
        _Pragma("unroll")                                                      \
        for (int i = 0; i < 4; i++) {                                          \
            const int idx = tid + 256 * i;                                     \
            const int br = idx >> 4, bc = idx & 15;                            \
            cp16(sbase + so_ + ATILE_B + (uint32_t)(br * GPB + bc * 8) * 2,    \
                 W + (size_t)(k0_ + br) * N + bn + bc * 8);                    \
        }                                                                      \
    }

    // ldmatrix lane maps
    const int lr = lane & 7, sel = lane >> 3;
    const int aro = (sel & 1) * 8 + lr, aco = (sel >> 1) * 8;
    uint32_t a_lm[4];
#pragma unroll
    for (int mt = 0; mt < 4; mt++)
        a_lm[mt] = sbase + (uint32_t)((wm + mt * 16 + aro) * GPA + aco) * 2;
    const int vro = (sel & 1) * 8 + lr, vco = (sel >> 1) * 8;
    uint32_t b_lm[2];
#pragma unroll
    for (int p = 0; p < 2; p++)
        b_lm[p] = sbase + ATILE_B +
                  (uint32_t)(vro * GPB + wn + p * 16 + vco) * 2;

    const int nk = K / KTILE;
    GI(0, 0) cp_commit();
    GI(1, 1) cp_commit();

    int csl = 0, isl = 2;
    for (int kt = 0; kt < nk; kt++) {
        cp_wait1();
        __syncthreads();
        if (kt + 2 < nk) { GI(isl, kt + 2) isl = (isl == 2) ? 0 : isl + 1; }
        cp_commit();

        const uint32_t so = (uint32_t)csl * STG_B;
#pragma unroll
        for (int ks = 0; ks < 4; ks++) {
            uint32_t af[4][4];
#pragma unroll
            for (int mt = 0; mt < 4; mt++)
                ldm_x4(af[mt], a_lm[mt] + so + ks * 32);
            uint32_t bf[2][4];
            ldm_x4_t(bf[0], b_lm[0] + so + ks * (16 * GPB * 2));
            ldm_x4_t(bf[1], b_lm[1] + so + ks * (16 * GPB * 2));
#pragma unroll
            for (int mt = 0; mt < 4; mt++)
#pragma unroll
                for (int nt = 0; nt < 4; nt++)
                    mma_f16(acc[mt][nt], af[mt], &bf[nt >> 1][(nt & 1) * 2]);
        }
        csl = (csl == 2) ? 0 : csl + 1;
    }
#undef GI

    // epilogue
#pragma unroll
    for (int mt = 0; mt < 4; mt++) {
        const int r = bm + wm + mt * 16 + g;
#pragma unroll
        for (int nt = 0; nt < 4; nt++) {
            const int c = bn + wn + nt * 8 + 2 * t;
            const float2 bb = *(const float2*)(bias + c);
            float2 v0, v1;
            v0.x = (acc[mt][nt][0] + bb.x) * oscale;
            v0.y = (acc[mt][nt][1] + bb.y) * oscale;
            v1.x = (acc[mt][nt][2] + bb.x) * oscale;
            v1.y = (acc[mt][nt][3] + bb.y) * oscale;
            if (EPI == 1) {
                v0.x = fmaxf(v0.x, 0.f); v0.y = fmaxf(v0.y, 0.f);
                v1.x = fmaxf(v1.x, 0.f); v1.y = fmaxf(v1.y, 0.f);
            }
            if (EPI == 2) {
                const float2 q0r = *(const float2*)(res + (size_t)r * N + c);
                const float2 q1r = *(const float2*)(res + (size_t)(r + 8) * N + c);
                v0.x += q0r.x; v0.y += q0r.y;
                v1.x += q1r.x; v1.y += q1r.y;
            }
            if (OUTH) {
                __half* C = (__half*)Cv;
                *(__half2*)(C + (size_t)r * N + c)       = __floats2half2_rn(v0.x, v0.y);
                *(__half2*)(C + (size_t)(r + 8) * N + c) = __floats2half2_rn(v1.x, v1.y);
            } else {
                float* C = (float*)Cv;
                *(float2*)(C + (size_t)r * N + c)       = v0;
                *(float2*)(C + (size_t)(r + 8) * N + c) = v1;
            }
        }
    }
}

template <int EPI, int OUTH>
__global__ __launch_bounds__(256, 2)
void gemm_tc(const __half* __restrict__ A, const __half* __restrict__ W,
             const float* __restrict__ bias, const float* __restrict__ res,
             void* __restrict__ C, int N, int K)
{
    gemm_body<EPI, OUTH>(A, W, bias, res, C, N, K,
                         blockIdx.y * 128, blockIdx.x * 128, 1.f);
}

// fused QKV: gridDim.z = 3; Q output pre-scaled by 1/sqrt(DK) = 0.125
__global__ __launch_bounds__(256, 2)
void qkv_tc(const __half* __restrict__ xH, const __half* __restrict__ wqkvH,
            const float* __restrict__ bq, const float* __restrict__ bk,
            const float* __restrict__ bv, __half* __restrict__ qkvH)
{
    const int z = blockIdx.z;
    const float* bias = (z == 0) ? bq : (z == 1) ? bk : bv;
    gemm_body<0, 1>(xH, wqkvH + (size_t)z * D_MODEL * D_MODEL, bias, nullptr,
                    qkvH + (size_t)z * MTOT * D_MODEL, D_MODEL, D_MODEL,
                    blockIdx.y * 128, blockIdx.x * 128,
                    (z == 0) ? 0.125f : 1.f);
}

// ---------------------------------------------------------------------------
// Fused pre-pass: ALL fp32 -> fp16 converts in one launch.
// Segments (blocks of 256 threads x 1 float4): x 4096 | wq 1024 | wk 1024 |
// wv 1024 | wo 1024 | w1 4096 | w2 4096  -> grid 16384.
// ---------------------------------------------------------------------------
__global__ __launch_bounds__(256)
void cvt_all(const float* __restrict__ x,  const float* __restrict__ wq,
             const float* __restrict__ wk, const float* __restrict__ wv,
             const float* __restrict__ wo, const float* __restrict__ w1,
             const float* __restrict__ w2,
             __half* __restrict__ xH, __half* __restrict__ wqkvH,
             __half* __restrict__ woH, __half* __restrict__ w1H,
             __half* __restrict__ w2H)
{
    const int bid = blockIdx.x;
    const float* src;
    __half* dst;
    int off;
    if      (bid < 4096)  { src = x;  dst = xH;                      off = bid; }
    else if (bid < 5120)  { src = wq; dst = wqkvH;                   off = bid - 4096; }
    else if (bid < 6144)  { src = wk; dst = wqkvH + D_MODEL*D_MODEL; off = bid - 5120; }
    else if (bid < 7168)  { src = wv; dst = wqkvH + 2*D_MODEL*D_MODEL; off = bid - 6144; }
    else if (bid < 8192)  { src = wo; dst = woH;                     off = bid - 7168; }
    else if (bid < 12288) { src = w1; dst = w1H;                     off = bid - 8192; }
    else                  { src = w2; dst = w2H;                     off = bid - 12288; }

    const int i = off * 256 + threadIdx.x;
    float4 v = ((const float4*)src)[i];
    __half2 h0 = __floats2half2_rn(v.x, v.y);
    __half2 h1 = __floats2half2_rn(v.z, v.w);
    uint2 u;
    u.x = *(uint32_t*)&h0;
    u.y = *(uint32_t*)&h1;
    ((uint2*)dst)[i] = u;
}

// ---------------------------------------------------------------------------
// fp16 flash attention — unchanged from R9 (proven).
// ---------------------------------------------------------------------------
#define AQT 128
#define AKT 64
#define PH  72
#define QH  (AQT * PH)
#define KVST (2 * AKT * PH)
#define PS_H (QH + 3 * KVST)
#define ATTN_SMEM ((PS_H + AQT * PH) * 2)   // 92160 bytes

__global__ __launch_bounds__(256, 2)
void attn_tc(const __half* __restrict__ Q, const __half* __restrict__ K,
             const __half* __restrict__ V, __half* __restrict__ O)
{
    extern __shared__ uint32_t asmem[];
    __half* smh = (__half*)asmem;

    const int tid  = threadIdx.x;
    const int wid  = tid >> 5;
    const int lane = tid & 31;
    const int g    = lane >> 2;
    const int t    = lane & 3;
    const int bh   = blockIdx.y;
    const int b    = bh >> 4;
    const int h    = bh & 15;
    const int q0   = blockIdx.x * AQT;
    const size_t base = (size_t)b * SEQ * D_MODEL + (size_t)h * DK;

#pragma unroll
    for (int e = 0; e < 4; e++) {
        int idx = tid + 256 * e;
        int r = idx >> 3, ch = idx & 7;
        ((uint4*)(smh + r * PH))[ch] =
            *((const uint4*)(Q + base + (size_t)(q0 + r) * D_MODEL) + ch);
    }

    float m0 = -1e30f, m1 = -1e30f, l0 = 0.f, l1 = 0.f;
    float oacc[8][4];
#pragma unroll
    for (int nt = 0; nt < 8; nt++)
#pragma unroll
        for (int e = 0; e < 4; e++) oacc[nt][e] = 0.f;

    const int qrow = wid * 16;

    const int kvr = tid >> 3, kvc = tid & 7;
    const uint32_t sb = (uint32_t)__cvta_generic_to_shared(asmem);
    const uint32_t kS = sb + (uint32_t)QH * 2 + (uint32_t)(kvr * PH + kvc * 8) * 2;

#define CPKV(slot, kt_)                                                        \
    {                                                                          \
        const uint32_t so_ = (uint32_t)(slot) * (KVST * 2);                    \
        const size_t gr0 = base + (size_t)((kt_) * AKT + kvr) * D_MODEL;       \
        const size_t gr1 = gr0 + (size_t)32 * D_MODEL;                         \
        cp16(kS + so_, K + gr0 + kvc * 8);                                     \
        cp16(kS + so_ + 32 * PH * 2, K + gr1 + kvc * 8);                       \
        cp16(kS + so_ + AKT * PH * 2, V + gr0 + kvc * 8);                      \
        cp16(kS + so_ + AKT * PH * 2 + 32 * PH * 2, V + gr1 + kvc * 8);        \
    }

    const int lr = lane & 7, sel = lane >> 3;
    const int aro = (sel & 1) * 8 + lr, aco = (sel >> 1) * 8;
    const int bro = (sel >> 1) * 8 + lr, bco = (sel & 1) * 8;
    const int vro = (sel & 1) * 8 + lr, vco = (sel >> 1) * 8;
    const uint32_t q_lm = sb + (uint32_t)((qrow + aro) * PH + aco) * 2;
    const uint32_t p_lm = sb + (uint32_t)(PS_H + (qrow + aro) * PH + aco) * 2;
    uint32_t k_lm[4], v_lm[4];
#pragma unroll
    for (int p = 0; p < 4; p++) {
        k_lm[p] = (uint32_t)((p * 16 + bro) * PH + bco) * 2;
        v_lm[p] = (uint32_t)(vro * PH + p * 16 + vco) * 2;
    }

    const int nk = SEQ / AKT;
    CPKV(0, 0) cp_commit();
    CPKV(1, 1) cp_commit();

    int csl = 0, isl = 2;
    for (int kt = 0; kt < nk; kt++) {
        cp_wait1();
        __syncthreads();
        if (kt + 2 < nk) { CPKV(isl, kt + 2) isl = (isl == 2) ? 0 : isl + 1; }
        cp_commit();

        const uint32_t kb = (uint32_t)QH * 2 + (uint32_t)csl * (KVST * 2);
        const uint32_t vb = kb + (uint32_t)(AKT * PH) * 2;

        float sacc[8][4];
#pragma unroll
        for (int nt = 0; nt < 8; nt++)
#pragma unroll
            for (int e = 0; e < 4; e++) sacc[nt][e] = 0.f;

#pragma unroll
        for (int ks = 0; ks < 4; ks++) {
            uint32_t a[4];
            ldm_x4(a, q_lm + ks * 32);
            uint32_t kf[4][4];
#pragma unroll
            for (int p = 0; p < 4; p++)
                ldm_x4(kf[p], sb + kb + k_lm[p] + ks * 32);
#pragma unroll
            for (int nt = 0; nt < 8; nt++)
                mma_f16(sacc[nt], a, &kf[nt >> 1][(nt & 1) * 2]);
        }

        float rmax0 = -1e30f, rmax1 = -1e30f;
#pragma unroll
        for (int nt = 0; nt < 8; nt++) {
            rmax0 = fmaxf(rmax0, fmaxf(sacc[nt][0], sacc[nt][1]));
            rmax1 = fmaxf(rmax1, fmaxf(sacc[nt][2], sacc[nt][3]));
        }
        rmax0 = fmaxf(rmax0, __shfl_xor_sync(0xffffffffu, rmax0, 1));
        rmax0 = fmaxf(rmax0, __shfl_xor_sync(0xffffffffu, rmax0, 2));
        rmax1 = fmaxf(rmax1, __shfl_xor_sync(0xffffffffu, rmax1, 1));
        rmax1 = fmaxf(rmax1, __shfl_xor_sync(0xffffffffu, rmax1, 2));

        const float nm0 = fmaxf(m0, rmax0);
        const float nm1 = fmaxf(m1, rmax1);
        const float sc0 = __expf(m0 - nm0);
        const float sc1 = __expf(m1 - nm1);

        float rs0 = 0.f, rs1 = 0.f;
        __half* ps0 = smh + PS_H + (qrow + g) * PH;
        __half* ps1 = smh + PS_H + (qrow + g + 8) * PH;
#pragma unroll
        for (int nt = 0; nt < 8; nt++) {
            float p00 = __expf(sacc[nt][0] - nm0);
            float p01 = __expf(sacc[nt][1] - nm0);
            float p10 = __expf(sacc[nt][2] - nm1);
            float p11 = __expf(sacc[nt][3] - nm1);
            rs0 += p00 + p01;
            rs1 += p10 + p11;
            *(__half2*)(ps0 + nt * 8 + 2 * t) = __floats2half2_rn(p00, p01);
            *(__half2*)(ps1 + nt * 8 + 2 * t) = __floats2half2_rn(p10, p11);
        }
        rs0 += __shfl_xor_sync(0xffffffffu, rs0, 1);
        rs0 += __shfl_xor_sync(0xffffffffu, rs0, 2);
        rs1 += __shfl_xor_sync(0xffffffffu, rs1, 1);
        rs1 += __shfl_xor_sync(0xffffffffu, rs1, 2);

        m0 = nm0; m1 = nm1;
        l0 = l0 * sc0 + rs0;
        l1 = l1 * sc1 + rs1;
#pragma unroll
        for (int nt = 0; nt < 8; nt++) {
            oacc[nt][0] *= sc0; oacc[nt][1] *= sc0;
            oacc[nt][2] *= sc1; oacc[nt][3] *= sc1;
        }

        __syncwarp();

#pragma unroll
        for (int ks = 0; ks < 4; ks++) {
            uint32_t a[4];
            ldm_x4(a, p_lm + ks * 32);
            uint32_t vf[4][4];
#pragma unroll
            for (int p = 0; p < 4; p++)
                ldm_x4_t(vf[p], sb + vb + v_lm[p] + ks * (16 * PH * 2));
#pragma unroll
            for (int nt = 0; nt < 8; nt++)
                mma_f16(oacc[nt], a, &vf[nt >> 1][(nt & 1) * 2]);
        }

        csl = (csl == 2) ? 0 : csl + 1;
    }
#undef CPKV

    const float il0 = 1.f / l0;
    const float il1 = 1.f / l1;
#pragma unroll
    for (int nt = 0; nt < 8; nt++) {
        const int c = nt * 8 + 2 * t;
        __half2 u0 = __floats2half2_rn(oacc[nt][0] * il0, oacc[nt][1] * il0);
        __half2 u1 = __floats2half2_rn(oacc[nt][2] * il1, oacc[nt][3] * il1);
        *(__half2*)(O + base + (size_t)(q0 + qrow + g    ) * D_MODEL + c) = u0;
        *(__half2*)(O + base + (size_t)(q0 + qrow + g + 8) * D_MODEL + c) = u1;
    }
}

// ---------------------------------------------------------------------------
// LayerNorm over last dim (1024), float4 path; optional fp16 copy output.
// ---------------------------------------------------------------------------
__global__ __launch_bounds__(256)
void ln_kernel(const float* __restrict__ X, const float* __restrict__ g,
               const float* __restrict__ b, float* __restrict__ Y,
               __half* __restrict__ Yh)
{
    const int row = blockIdx.x;
    const int tid = threadIdx.x;
    const float4 v = *((const float4*)(X + (size_t)row * D_MODEL) + tid);

    float s  = v.x + v.y + v.z + v.w;
    float s2 = v.x * v.x + v.y * v.y + v.z * v.z + v.w * v.w;
#pragma unroll
    for (int off = 16; off; off >>= 1) {
        s  += __shfl_xor_sync(0xffffffffu, s,  off);
        s2 += __shfl_xor_sync(0xffffffffu, s2, off);
    }
    __shared__ float rs[8], rs2[8];
    const int w = tid >> 5, lane = tid & 31;
    if (lane == 0) { rs[w] = s; rs2[w] = s2; }
    __syncthreads();
    s = 0.f; s2 = 0.f;
#pragma unroll
    for (int i = 0; i < 8; i++) { s += rs[i]; s2 += rs2[i]; }

    const float mean = s * (1.f / D_MODEL);
    const float var  = s2 * (1.f / D_MODEL) - mean * mean;
    const float rstd = rsqrtf(var + 1e-5f);

    const float4 gg = *((const float4*)g + tid);
    const float4 bb = *((const float4*)b + tid);
    float4 y;
    y.x = (v.x - mean) * rstd * gg.x + bb.x;
    y.y = (v.y - mean) * rstd * gg.y + bb.y;
    y.z = (v.z - mean) * rstd * gg.z + bb.z;
    y.w = (v.w - mean) * rstd * gg.w + bb.w;
    *((float4*)(Y + (size_t)row * D_MODEL) + tid) = y;
    if (Yh) {
        __half2 h0 = __floats2half2_rn(y.x, y.y);
        __half2 h1 = __floats2half2_rn(y.z, y.w);
        uint2 u;
        u.x = *(uint32_t*)&h0;
        u.y = *(uint32_t*)&h1;
        *((uint2*)(Yh + (size_t)row * D_MODEL) + tid) = u;
    }
}

// ---------------------------------------------------------------------------
// Launch
// ---------------------------------------------------------------------------
extern "C" void kernel_launch(void* const* d_in, const int* in_sizes, int n_in,
                              void* d_out, int out_size)
{
    const float* x     = (const float*)d_in[0];
    const float* wq    = (const float*)d_in[1];
    const float* bq    = (const float*)d_in[2];
    const float* wk    = (const float*)d_in[3];
    const float* bk    = (const float*)d_in[4];
    const float* wv    = (const float*)d_in[5];
    const float* bv    = (const float*)d_in[6];
    const float* wo    = (const float*)d_in[7];
    const float* bo    = (const float*)d_in[8];
    const float* ln1_g = (const float*)d_in[9];
    const float* ln1_b = (const float*)d_in[10];
    const float* ln2_g = (const float*)d_in[11];
    const float* ln2_b = (const float*)d_in[12];
    const float* w1    = (const float*)d_in[13];
    const float* b1    = (const float*)d_in[14];
    const float* w2    = (const float*)d_in[15];
    const float* b2    = (const float*)d_in[16];
    float* out = (float*)d_out;

    float *x1, *tmp;
    __half *qkvH, *attnH, *x1H, *hH, *xH, *wqkvH, *woH, *w1H, *w2H;
    cudaGetSymbolAddress((void**)&qkvH,  g_qkvH);
    cudaGetSymbolAddress((void**)&attnH, g_attnH);
    cudaGetSymbolAddress((void**)&x1,    g_x1);
    cudaGetSymbolAddress((void**)&x1H,   g_x1H);
    cudaGetSymbolAddress((void**)&tmp,   g_tmp);
    cudaGetSymbolAddress((void**)&hH,    g_hH);
    cudaGetSymbolAddress((void**)&xH,    g_xH);
    cudaGetSymbolAddress((void**)&wqkvH, g_wqkvH);
    cudaGetSymbolAddress((void**)&woH,   g_woH);
    cudaGetSymbolAddress((void**)&w1H,   g_w1H);
    cudaGetSymbolAddress((void**)&w2H,   g_w2H);

    cudaFuncSetAttribute(attn_tc, cudaFuncAttributeMaxDynamicSharedMemorySize,
                         ATTN_SMEM);
    cudaFuncSetAttribute(qkv_tc, cudaFuncAttributeMaxDynamicSharedMemorySize,
                         GEMM_SMEM);
    cudaFuncSetAttribute(gemm_tc<2, 0>, cudaFuncAttributeMaxDynamicSharedMemorySize,
                         GEMM_SMEM);
    cudaFuncSetAttribute(gemm_tc<1, 1>, cudaFuncAttributeMaxDynamicSharedMemorySize,
                         GEMM_SMEM);

    const dim3 blk(256);

    // fused pre-pass: all fp32 -> fp16 converts in one launch
    cvt_all<<<16384, blk>>>(x, wq, wk, wv, wo, w1, w2,
                            xH, wqkvH, woH, w1H, w2H);

    // QKV (fused, z = 0/1/2), Q pre-scaled by 0.125
    qkv_tc<<<dim3(D_MODEL / 128, MTOT / 128, 3), blk, GEMM_SMEM>>>(
        xH, wqkvH, bq, bk, bv, qkvH);

    // attention
    attn_tc<<<dim3(SEQ / AQT, BATCH * NH), blk, ATTN_SMEM>>>(
        qkvH, qkvH + (size_t)MTOT * D_MODEL, qkvH + (size_t)2 * MTOT * D_MODEL,
        attnH);

    // O-proj + residual -> LN1
    gemm_tc<2, 0><<<dim3(D_MODEL / 128, MTOT / 128), blk, GEMM_SMEM>>>(
        attnH, woH, bo, x, tmp, D_MODEL, D_MODEL);
    ln_kernel<<<MTOT, blk>>>(tmp, ln1_g, ln1_b, x1, x1H);

    // FFN
    gemm_tc<1, 1><<<dim3(DFF / 128, MTOT / 128), blk, GEMM_SMEM>>>(
        x1H, w1H, b1, nullptr, hH, DFF, D_MODEL);
    gemm_tc<2, 0><<<dim3(D_MODEL / 128, MTOT / 128), blk, GEMM_SMEM>>>(
        hH, w2H, b2, x1, tmp, D_MODEL, DFF);
    ln_kernel<<<MTOT, blk>>>(tmp, ln2_g, ln2_b, out, nullptr);
}

// round 11
// speedup vs baseline: 1.9755x; 1.0257x over previous
#include <cuda_runtime.h>
#include <cuda_fp16.h>
#include <cstdint>
#include <cstddef>

// Problem dims (fixed by the reference)
#define D_MODEL 1024
#define SEQ     2048
#define BATCH   2
#define NH      16
#define DK      64
#define DFF     4096
#define MTOT    (BATCH * SEQ)   // 4096 rows

// ---------------------------------------------------------------------------
// Scratch (no allocation allowed -> __device__ globals)
// ---------------------------------------------------------------------------
__device__ __half g_qkvH [3 * MTOT * D_MODEL];  // q|k|v (q pre-scaled by log2e/8)
__device__ __half g_attnH[MTOT * D_MODEL];      // attn out, fp16
__device__ float  g_x1   [MTOT * D_MODEL];
__device__ __half g_x1H  [MTOT * D_MODEL];
__device__ float  g_tmp  [MTOT * D_MODEL];
__device__ __half g_hH   [MTOT * DFF];          // relu(ffn1), fp16
__device__ __half g_xH   [MTOT * D_MODEL];      // x, fp16
__device__ __half g_wqkvH[3 * D_MODEL * D_MODEL];   // [K][N] (no transpose)
__device__ __half g_woH  [D_MODEL * D_MODEL];
__device__ __half g_w1H  [D_MODEL * DFF];
__device__ __half g_w2H  [DFF * D_MODEL];

// ---------------------------------------------------------------------------
// helpers
// ---------------------------------------------------------------------------
__device__ __forceinline__ void mma_f16(float c[4], const uint32_t a[4],
                                        const uint32_t b[2]) {
    asm("mma.sync.aligned.m16n8k16.row.col.f32.f16.f16.f32 "
        "{%0,%1,%2,%3}, {%4,%5,%6,%7}, {%8,%9}, {%0,%1,%2,%3};"
        : "+f"(c[0]), "+f"(c[1]), "+f"(c[2]), "+f"(c[3])
        : "r"(a[0]), "r"(a[1]), "r"(a[2]), "r"(a[3]), "r"(b[0]), "r"(b[1]));
}

__device__ __forceinline__ void ldm_x4(uint32_t r[4], uint32_t addr) {
    asm volatile("ldmatrix.sync.aligned.m8n8.x4.shared.b16 {%0,%1,%2,%3}, [%4];"
                 : "=r"(r[0]), "=r"(r[1]), "=r"(r[2]), "=r"(r[3]) : "r"(addr));
}
__device__ __forceinline__ void ldm_x4_t(uint32_t r[4], uint32_t addr) {
    asm volatile("ldmatrix.sync.aligned.m8n8.x4.trans.shared.b16 {%0,%1,%2,%3}, [%4];"
                 : "=r"(r[0]), "=r"(r[1]), "=r"(r[2]), "=r"(r[3]) : "r"(addr));
}

__device__ __forceinline__ void cp16(uint32_t saddr, const void* gptr) {
    asm volatile("cp.async.cg.shared.global [%0], [%1], 16;"
                 :: "r"(saddr), "l"(gptr));
}
__device__ __forceinline__ void cp_commit() { asm volatile("cp.async.commit_group;"); }
__device__ __forceinline__ void cp_wait1()  { asm volatile("cp.async.wait_group 1;"); }

// paired fp16 exp2 on MUFU: one instruction for two values
__device__ __forceinline__ uint32_t ex2_f16x2(float lo, float hi) {
    __half2 h = __floats2half2_rn(lo, hi);
    uint32_t r;
    asm("ex2.approx.f16x2 %0, %1;" : "=r"(r) : "r"(*(uint32_t*)&h));
    return r;
}

// ---------------------------------------------------------------------------
// fp16 tensor-core GEMM — unchanged from R10 (proven).
// ---------------------------------------------------------------------------
#define KTILE 64
#define GPA 72
#define GPB 136
#define ATILE_B (128 * GPA * 2)
#define BTILE_B (KTILE * GPB * 2)
#define STG_B   (ATILE_B + BTILE_B)
#define GEMM_SMEM (3 * STG_B)        // 107520

template <int EPI, int OUTH>
__device__ __forceinline__ void gemm_body(
    const __half* __restrict__ A, const __half* __restrict__ W,
    const float* __restrict__ bias, const float* __restrict__ res,
    void* __restrict__ Cv, int N, int K, int bm, int bn, float oscale)
{
    extern __shared__ uint32_t gsm[];

    const int tid  = threadIdx.x;
    const int wid  = tid >> 5;
    const int lane = tid & 31;
    const int g    = lane >> 2;
    const int t    = lane & 3;
    const int wm   = (wid & 1) * 64;
    const int wn   = (wid >> 1) * 32;

    float acc[4][4][4];
#pragma unroll
    for (int i = 0; i < 4; i++)
#pragma unroll
        for (int j = 0; j < 4; j++)
#pragma unroll
            for (int e = 0; e < 4; e++) acc[i][j][e] = 0.f;

    const uint32_t sbase = (uint32_t)__cvta_generic_to_shared(gsm);

#define GI(slot, kt_)                                                          \
    {                                                                          \
        const uint32_t so_ = (uint32_t)(slot) * STG_B;                         \
        const int k0_ = (kt_) * KTILE;                                         \
        _Pragma("unroll")                                                      \
        for (int i = 0; i < 4; i++) {                                          \
            const int idx = tid + 256 * i;                                     \
            const int ar = idx >> 3, ac = idx & 7;                             \
            cp16(sbase + so_ + (uint32_t)(ar * GPA + ac * 8) * 2,              \
                 A + (size_t)(bm + ar) * K + k0_ + ac * 8);                    \
        }                                                                      \
        _Pragma("unroll")                                                      \
        for (int i = 0; i < 4; i++) {                                          \
            const int idx = tid + 256 * i;                                     \
            const int br = idx >> 4, bc = idx & 15;                            \
            cp16(sbase + so_ + ATILE_B + (uint32_t)(br * GPB + bc * 8) * 2,    \
                 W + (size_t)(k0_ + br) * N + bn + bc * 8);                    \
        }                                                                      \
    }

    const int lr = lane & 7, sel = lane >> 3;
    const int aro = (sel & 1) * 8 + lr, aco = (sel >> 1) * 8;
    uint32_t a_lm[4];
#pragma unroll
    for (int mt = 0; mt < 4; mt++)
        a_lm[mt] = sbase + (uint32_t)((wm + mt * 16 + aro) * GPA + aco) * 2;
    const int vro = (sel & 1) * 8 + lr, vco = (sel >> 1) * 8;
    uint32_t b_lm[2];
#pragma unroll
    for (int p = 0; p < 2; p++)
        b_lm[p] = sbase + ATILE_B +
                  (uint32_t)(vro * GPB + wn + p * 16 + vco) * 2;

    const int nk = K / KTILE;
    GI(0, 0) cp_commit();
    GI(1, 1) cp_commit();

    int csl = 0, isl = 2;
    for (int kt = 0; kt < nk; kt++) {
        cp_wait1();
        __syncthreads();
        if (kt + 2 < nk) { GI(isl, kt + 2) isl = (isl == 2) ? 0 : isl + 1; }
        cp_commit();

        const uint32_t so = (uint32_t)csl * STG_B;
#pragma unroll
        for (int ks = 0; ks < 4; ks++) {
            uint32_t af[4][4];
#pragma unroll
            for (int mt = 0; mt < 4; mt++)
                ldm_x4(af[mt], a_lm[mt] + so + ks * 32);
            uint32_t bf[2][4];
            ldm_x4_t(bf[0], b_lm[0] + so + ks * (16 * GPB * 2));
            ldm_x4_t(bf[1], b_lm[1] + so + ks * (16 * GPB * 2));
#pragma unroll
            for (int mt = 0; mt < 4; mt++)
#pragma unroll
                for (int nt = 0; nt < 4; nt++)
                    mma_f16(acc[mt][nt], af[mt], &bf[nt >> 1][(nt & 1) * 2]);
        }
        csl = (csl == 2) ? 0 : csl + 1;
    }
#undef GI

#pragma unroll
    for (int mt = 0; mt < 4; mt++) {
        const int r = bm + wm + mt * 16 + g;
#pragma unroll
        for (int nt = 0; nt < 4; nt++) {
            const int c = bn + wn + nt * 8 + 2 * t;
            const float2 bb = *(const float2*)(bias + c);
            float2 v0, v1;
            v0.x = (acc[mt][nt][0] + bb.x) * oscale;
            v0.y = (acc[mt][nt][1] + bb.y) * oscale;
            v1.x = (acc[mt][nt][2] + bb.x) * oscale;
            v1.y = (acc[mt][nt][3] + bb.y) * oscale;
            if (EPI == 1) {
                v0.x = fmaxf(v0.x, 0.f); v0.y = fmaxf(v0.y, 0.f);
                v1.x = fmaxf(v1.x, 0.f); v1.y = fmaxf(v1.y, 0.f);
            }
            if (EPI == 2) {
                const float2 q0r = *(const float2*)(res + (size_t)r * N + c);
                const float2 q1r = *(const float2*)(res + (size_t)(r + 8) * N + c);
                v0.x += q0r.x; v0.y += q0r.y;
                v1.x += q1r.x; v1.y += q1r.y;
            }
            if (OUTH) {
                __half* C = (__half*)Cv;
                *(__half2*)(C + (size_t)r * N + c)       = __floats2half2_rn(v0.x, v0.y);
                *(__half2*)(C + (size_t)(r + 8) * N + c) = __floats2half2_rn(v1.x, v1.y);
            } else {
                float* C = (float*)Cv;
                *(float2*)(C + (size_t)r * N + c)       = v0;
                *(float2*)(C + (size_t)(r + 8) * N + c) = v1;
            }
        }
    }
}

template <int EPI, int OUTH>
__global__ __launch_bounds__(256, 2)
void gemm_tc(const __half* __restrict__ A, const __half* __restrict__ W,
             const float* __restrict__ bias, const float* __restrict__ res,
             void* __restrict__ C, int N, int K)
{
    gemm_body<EPI, OUTH>(A, W, bias, res, C, N, K,
                         blockIdx.y * 128, blockIdx.x * 128, 1.f);
}

// fused QKV: gridDim.z = 3; Q pre-scaled by log2e/sqrt(DK) (log2-domain scores)
__global__ __launch_bounds__(256, 2)
void qkv_tc(const __half* __restrict__ xH, const __half* __restrict__ wqkvH,
            const float* __restrict__ bq, const float* __restrict__ bk,
            const float* __restrict__ bv, __half* __restrict__ qkvH)
{
    const int z = blockIdx.z;
    const float* bias = (z == 0) ? bq : (z == 1) ? bk : bv;
    gemm_body<0, 1>(xH, wqkvH + (size_t)z * D_MODEL * D_MODEL, bias, nullptr,
                    qkvH + (size_t)z * MTOT * D_MODEL, D_MODEL, D_MODEL,
                    blockIdx.y * 128, blockIdx.x * 128,
                    (z == 0) ? 0.125f * 1.4426950408889634f : 1.f);
}

// ---------------------------------------------------------------------------
// Fused pre-pass: ALL fp32 -> fp16 converts in one launch. (R10-proven)
// ---------------------------------------------------------------------------
__global__ __launch_bounds__(256)
void cvt_all(const float* __restrict__ x,  const float* __restrict__ wq,
             const float* __restrict__ wk, const float* __restrict__ wv,
             const float* __restrict__ wo, const float* __restrict__ w1,
             const float* __restrict__ w2,
             __half* __restrict__ xH, __half* __restrict__ wqkvH,
             __half* __restrict__ woH, __half* __restrict__ w1H,
             __half* __restrict__ w2H)
{
    const int bid = blockIdx.x;
    const float* src;
    __half* dst;
    int off;
    if      (bid < 4096)  { src = x;  dst = xH;                      off = bid; }
    else if (bid < 5120)  { src = wq; dst = wqkvH;                   off = bid - 4096; }
    else if (bid < 6144)  { src = wk; dst = wqkvH + D_MODEL*D_MODEL; off = bid - 5120; }
    else if (bid < 7168)  { src = wv; dst = wqkvH + 2*D_MODEL*D_MODEL; off = bid - 6144; }
    else if (bid < 8192)  { src = wo; dst = woH;                     off = bid - 7168; }
    else if (bid < 12288) { src = w1; dst = w1H;                     off = bid - 8192; }
    else                  { src = w2; dst = w2H;                     off = bid - 12288; }

    const int i = off * 256 + threadIdx.x;
    float4 v = ((const float4*)src)[i];
    __half2 h0 = __floats2half2_rn(v.x, v.y);
    __half2 h1 = __floats2half2_rn(v.z, v.w);
    uint2 u;
    u.x = *(uint32_t*)&h0;
    u.y = *(uint32_t*)&h1;
    ((uint2*)dst)[i] = u;
}

// ---------------------------------------------------------------------------
// fp16 flash attention. Scores arrive in log2 domain (Q pre-scaled by
// log2e/8), so softmax uses ex2.approx.f16x2: one MUFU op per TWO P values,
// and the result is directly the fp16 P stored for the PV mma.
// ---------------------------------------------------------------------------
#define AQT 128
#define AKT 64
#define PH  72
#define QH  (AQT * PH)
#define KVST (2 * AKT * PH)
#define PS_H (QH + 3 * KVST)
#define ATTN_SMEM ((PS_H + AQT * PH) * 2)   // 92160 bytes

__global__ __launch_bounds__(256, 2)
void attn_tc(const __half* __restrict__ Q, const __half* __restrict__ K,
             const __half* __restrict__ V, __half* __restrict__ O)
{
    extern __shared__ uint32_t asmem[];
    __half* smh = (__half*)asmem;

    const int tid  = threadIdx.x;
    const int wid  = tid >> 5;
    const int lane = tid & 31;
    const int g    = lane >> 2;
    const int t    = lane & 3;
    const int bh   = blockIdx.y;
    const int b    = bh >> 4;
    const int h    = bh & 15;
    const int q0   = blockIdx.x * AQT;
    const size_t base = (size_t)b * SEQ * D_MODEL + (size_t)h * DK;

#pragma unroll
    for (int e = 0; e < 4; e++) {
        int idx = tid + 256 * e;
        int r = idx >> 3, ch = idx & 7;
        ((uint4*)(smh + r * PH))[ch] =
            *((const uint4*)(Q + base + (size_t)(q0 + r) * D_MODEL) + ch);
    }

    float m0 = -1e30f, m1 = -1e30f, l0 = 0.f, l1 = 0.f;
    float oacc[8][4];
#pragma unroll
    for (int nt = 0; nt < 8; nt++)
#pragma unroll
        for (int e = 0; e < 4; e++) oacc[nt][e] = 0.f;

    const int qrow = wid * 16;

    const int kvr = tid >> 3, kvc = tid & 7;
    const uint32_t sb = (uint32_t)__cvta_generic_to_shared(asmem);
    const uint32_t kS = sb + (uint32_t)QH * 2 + (uint32_t)(kvr * PH + kvc * 8) * 2;

#define CPKV(slot, kt_)                                                        \
    {                                                                          \
        const uint32_t so_ = (uint32_t)(slot) * (KVST * 2);                    \
        const size_t gr0 = base + (size_t)((kt_) * AKT + kvr) * D_MODEL;       \
        const size_t gr1 = gr0 + (size_t)32 * D_MODEL;                         \
        cp16(kS + so_, K + gr0 + kvc * 8);                                     \
        cp16(kS + so_ + 32 * PH * 2, K + gr1 + kvc * 8);                       \
        cp16(kS + so_ + AKT * PH * 2, V + gr0 + kvc * 8);                      \
        cp16(kS + so_ + AKT * PH * 2 + 32 * PH * 2, V + gr1 + kvc * 8);        \
    }

    const int lr = lane & 7, sel = lane >> 3;
    const int aro = (sel & 1) * 8 + lr, aco = (sel >> 1) * 8;
    const int bro = (sel >> 1) * 8 + lr, bco = (sel & 1) * 8;
    const int vro = (sel & 1) * 8 + lr, vco = (sel >> 1) * 8;
    const uint32_t q_lm = sb + (uint32_t)((qrow + aro) * PH + aco) * 2;
    const uint32_t p_lm = sb + (uint32_t)(PS_H + (qrow + aro) * PH + aco) * 2;
    uint32_t k_lm[4], v_lm[4];
#pragma unroll
    for (int p = 0; p < 4; p++) {
        k_lm[p] = (uint32_t)((p * 16 + bro) * PH + bco) * 2;
        v_lm[p] = (uint32_t)(vro * PH + p * 16 + vco) * 2;
    }

    const int nk = SEQ / AKT;
    CPKV(0, 0) cp_commit();
    CPKV(1, 1) cp_commit();

    int csl = 0, isl = 2;
    for (int kt = 0; kt < nk; kt++) {
        cp_wait1();
        __syncthreads();
        if (kt + 2 < nk) { CPKV(isl, kt + 2) isl = (isl == 2) ? 0 : isl + 1; }
        cp_commit();

        const uint32_t kb = (uint32_t)QH * 2 + (uint32_t)csl * (KVST * 2);
        const uint32_t vb = kb + (uint32_t)(AKT * PH) * 2;

        // ---- S(log2) = Q K^T ----
        float sacc[8][4];
#pragma unroll
        for (int nt = 0; nt < 8; nt++)
#pragma unroll
            for (int e = 0; e < 4; e++) sacc[nt][e] = 0.f;

#pragma unroll
        for (int ks = 0; ks < 4; ks++) {
            uint32_t a[4];
            ldm_x4(a, q_lm + ks * 32);
            uint32_t kf[4][4];
#pragma unroll
            for (int p = 0; p < 4; p++)
                ldm_x4(kf[p], sb + kb + k_lm[p] + ks * 32);
#pragma unroll
            for (int nt = 0; nt < 8; nt++)
                mma_f16(sacc[nt], a, &kf[nt >> 1][(nt & 1) * 2]);
        }

        // ---- online softmax (log2 domain, fp16x2 exp2) ----
        float rmax0 = -1e30f, rmax1 = -1e30f;
#pragma unroll
        for (int nt = 0; nt < 8; nt++) {
            rmax0 = fmaxf(rmax0, fmaxf(sacc[nt][0], sacc[nt][1]));
            rmax1 = fmaxf(rmax1, fmaxf(sacc[nt][2], sacc[nt][3]));
        }
        rmax0 = fmaxf(rmax0, __shfl_xor_sync(0xffffffffu, rmax0, 1));
        rmax0 = fmaxf(rmax0, __shfl_xor_sync(0xffffffffu, rmax0, 2));
        rmax1 = fmaxf(rmax1, __shfl_xor_sync(0xffffffffu, rmax1, 1));
        rmax1 = fmaxf(rmax1, __shfl_xor_sync(0xffffffffu, rmax1, 2));

        const float nm0 = fmaxf(m0, rmax0);
        const float nm1 = fmaxf(m1, rmax1);
        const float sc0 = exp2f(m0 - nm0);
        const float sc1 = exp2f(m1 - nm1);

        float rs0 = 0.f, rs1 = 0.f;
        __half* ps0 = smh + PS_H + (qrow + g) * PH;
        __half* ps1 = smh + PS_H + (qrow + g + 8) * PH;
#pragma unroll
        for (int nt = 0; nt < 8; nt++) {
            const uint32_t p0 = ex2_f16x2(sacc[nt][0] - nm0, sacc[nt][1] - nm0);
            const uint32_t p1 = ex2_f16x2(sacc[nt][2] - nm1, sacc[nt][3] - nm1);
            *(uint32_t*)(ps0 + nt * 8 + 2 * t) = p0;
            *(uint32_t*)(ps1 + nt * 8 + 2 * t) = p1;
            const float2 f0 = __half22float2(*(const __half2*)&p0);
            const float2 f1 = __half22float2(*(const __half2*)&p1);
            rs0 += f0.x + f0.y;
            rs1 += f1.x + f1.y;
        }
        rs0 += __shfl_xor_sync(0xffffffffu, rs0, 1);
        rs0 += __shfl_xor_sync(0xffffffffu, rs0, 2);
        rs1 += __shfl_xor_sync(0xffffffffu, rs1, 1);
        rs1 += __shfl_xor_sync(0xffffffffu, rs1, 2);

        m0 = nm0; m1 = nm1;
        l0 = l0 * sc0 + rs0;
        l1 = l1 * sc1 + rs1;
#pragma unroll
        for (int nt = 0; nt < 8; nt++) {
            oacc[nt][0] *= sc0; oacc[nt][1] *= sc0;
            oacc[nt][2] *= sc1; oacc[nt][3] *= sc1;
        }

        __syncwarp();   // ps written/read within the warp only

        // ---- O += P V : V via ldmatrix.trans ----
#pragma unroll
        for (int ks = 0; ks < 4; ks++) {
            uint32_t a[4];
            ldm_x4(a, p_lm + ks * 32);
            uint32_t vf[4][4];
#pragma unroll
            for (int p = 0; p < 4; p++)
                ldm_x4_t(vf[p], sb + vb + v_lm[p] + ks * (16 * PH * 2));
#pragma unroll
            for (int nt = 0; nt < 8; nt++)
                mma_f16(oacc[nt], a, &vf[nt >> 1][(nt & 1) * 2]);
        }

        csl = (csl == 2) ? 0 : csl + 1;
    }
#undef CPKV

    const float il0 = 1.f / l0;
    const float il1 = 1.f / l1;
#pragma unroll
    for (int nt = 0; nt < 8; nt++) {
        const int c = nt * 8 + 2 * t;
        __half2 u0 = __floats2half2_rn(oacc[nt][0] * il0, oacc[nt][1] * il0);
        __half2 u1 = __floats2half2_rn(oacc[nt][2] * il1, oacc[nt][3] * il1);
        *(__half2*)(O + base + (size_t)(q0 + qrow + g    ) * D_MODEL + c) = u0;
        *(__half2*)(O + base + (size_t)(q0 + qrow + g + 8) * D_MODEL + c) = u1;
    }
}

// ---------------------------------------------------------------------------
// LayerNorm over last dim (1024), float4 path; optional fp16 copy output.
// ---------------------------------------------------------------------------
__global__ __launch_bounds__(256)
void ln_kernel(const float* __restrict__ X, const float* __restrict__ g,
               const float* __restrict__ b, float* __restrict__ Y,
               __half* __restrict__ Yh)
{
    const int row = blockIdx.x;
    const int tid = threadIdx.x;
    const float4 v = *((const float4*)(X + (size_t)row * D_MODEL) + tid);

    float s  = v.x + v.y + v.z + v.w;
    float s2 = v.x * v.x + v.y * v.y + v.z * v.z + v.w * v.w;
#pragma unroll
    for (int off = 16; off; off >>= 1) {
        s  += __shfl_xor_sync(0xffffffffu, s,  off);
        s2 += __shfl_xor_sync(0xffffffffu, s2, off);
    }
    __shared__ float rs[8], rs2[8];
    const int w = tid >> 5, lane = tid & 31;
    if (lane == 0) { rs[w] = s; rs2[w] = s2; }
    __syncthreads();
    s = 0.f; s2 = 0.f;
#pragma unroll
    for (int i = 0; i < 8; i++) { s += rs[i]; s2 += rs2[i]; }

    const float mean = s * (1.f / D_MODEL);
    const float var  = s2 * (1.f / D_MODEL) - mean * mean;
    const float rstd = rsqrtf(var + 1e-5f);

    const float4 gg = *((const float4*)g + tid);
    const float4 bb = *((const float4*)b + tid);
    float4 y;
    y.x = (v.x - mean) * rstd * gg.x + bb.x;
    y.y = (v.y - mean) * rstd * gg.y + bb.y;
    y.z = (v.z - mean) * rstd * gg.z + bb.z;
    y.w = (v.w - mean) * rstd * gg.w + bb.w;
    *((float4*)(Y + (size_t)row * D_MODEL) + tid) = y;
    if (Yh) {
        __half2 h0 = __floats2half2_rn(y.x, y.y);
        __half2 h1 = __floats2half2_rn(y.z, y.w);
        uint2 u;
        u.x = *(uint32_t*)&h0;
        u.y = *(uint32_t*)&h1;
        *((uint2*)(Yh + (size_t)row * D_MODEL) + tid) = u;
    }
}

// ---------------------------------------------------------------------------
// Launch
// ---------------------------------------------------------------------------
extern "C" void kernel_launch(void* const* d_in, const int* in_sizes, int n_in,
                              void* d_out, int out_size)
{
    const float* x     = (const float*)d_in[0];
    const float* wq    = (const float*)d_in[1];
    const float* bq    = (const float*)d_in[2];
    const float* wk    = (const float*)d_in[3];
    const float* bk    = (const float*)d_in[4];
    const float* wv    = (const float*)d_in[5];
    const float* bv    = (const float*)d_in[6];
    const float* wo    = (const float*)d_in[7];
    const float* bo    = (const float*)d_in[8];
    const float* ln1_g = (const float*)d_in[9];
    const float* ln1_b = (const float*)d_in[10];
    const float* ln2_g = (const float*)d_in[11];
    const float* ln2_b = (const float*)d_in[12];
    const float* w1    = (const float*)d_in[13];
    const float* b1    = (const float*)d_in[14];
    const float* w2    = (const float*)d_in[15];
    const float* b2    = (const float*)d_in[16];
    float* out = (float*)d_out;

    float *x1, *tmp;
    __half *qkvH, *attnH, *x1H, *hH, *xH, *wqkvH, *woH, *w1H, *w2H;
    cudaGetSymbolAddress((void**)&qkvH,  g_qkvH);
    cudaGetSymbolAddress((void**)&attnH, g_attnH);
    cudaGetSymbolAddress((void**)&x1,    g_x1);
    cudaGetSymbolAddress((void**)&x1H,   g_x1H);
    cudaGetSymbolAddress((void**)&tmp,   g_tmp);
    cudaGetSymbolAddress((void**)&hH,    g_hH);
    cudaGetSymbolAddress((void**)&xH,    g_xH);
    cudaGetSymbolAddress((void**)&wqkvH, g_wqkvH);
    cudaGetSymbolAddress((void**)&woH,   g_woH);
    cudaGetSymbolAddress((void**)&w1H,   g_w1H);
    cudaGetSymbolAddress((void**)&w2H,   g_w2H);

    cudaFuncSetAttribute(attn_tc, cudaFuncAttributeMaxDynamicSharedMemorySize,
                         ATTN_SMEM);
    cudaFuncSetAttribute(qkv_tc, cudaFuncAttributeMaxDynamicSharedMemorySize,
                         GEMM_SMEM);
    cudaFuncSetAttribute(gemm_tc<2, 0>, cudaFuncAttributeMaxDynamicSharedMemorySize,
                         GEMM_SMEM);
    cudaFuncSetAttribute(gemm_tc<1, 1>, cudaFuncAttributeMaxDynamicSharedMemorySize,
                         GEMM_SMEM);

    const dim3 blk(256);

    // fused pre-pass: all fp32 -> fp16 converts in one launch
    cvt_all<<<16384, blk>>>(x, wq, wk, wv, wo, w1, w2,
                            xH, wqkvH, woH, w1H, w2H);

    // QKV (fused, z = 0/1/2), Q pre-scaled by log2e/8
    qkv_tc<<<dim3(D_MODEL / 128, MTOT / 128, 3), blk, GEMM_SMEM>>>(
        xH, wqkvH, bq, bk, bv, qkvH);

    // attention
    attn_tc<<<dim3(SEQ / AQT, BATCH * NH), blk, ATTN_SMEM>>>(
        qkvH, qkvH + (size_t)MTOT * D_MODEL, qkvH + (size_t)2 * MTOT * D_MODEL,
        attnH);

    // O-proj + residual -> LN1
    gemm_tc<2, 0><<<dim3(D_MODEL / 128, MTOT / 128), blk, GEMM_SMEM>>>(
        attnH, woH, bo, x, tmp, D_MODEL, D_MODEL);
    ln_kernel<<<MTOT, blk>>>(tmp, ln1_g, ln1_b, x1, x1H);

    // FFN
    gemm_tc<1, 1><<<dim3(DFF / 128, MTOT / 128), blk, GEMM_SMEM>>>(
        x1H, w1H, b1, nullptr, hH, DFF, D_MODEL);
    gemm_tc<2, 0><<<dim3(D_MODEL / 128, MTOT / 128), blk, GEMM_SMEM>>>(
        hH, w2H, b2, x1, tmp, D_MODEL, DFF);
    ln_kernel<<<MTOT, blk>>>(tmp, ln2_g, ln2_b, out, nullptr);
}

// round 12
// speedup vs baseline: 2.0232x; 1.0241x over previous
#include <cuda_runtime.h>
#include <cuda_fp16.h>
#include <cstdint>
#include <cstddef>

// Problem dims (fixed by the reference)
#define D_MODEL 1024
#define SEQ     2048
#define BATCH   2
#define NH      16
#define DK      64
#define DFF     4096
#define MTOT    (BATCH * SEQ)   // 4096 rows

// ---------------------------------------------------------------------------
// Scratch (no allocation allowed -> __device__ globals)
// ---------------------------------------------------------------------------
__device__ __half g_qkvH [3 * MTOT * D_MODEL];  // q|k|v (q pre-scaled by log2e/8)
__device__ __half g_attnH[MTOT * D_MODEL];      // attn out, fp16
__device__ float  g_x1   [MTOT * D_MODEL];
__device__ __half g_x1H  [MTOT * D_MODEL];
__device__ float  g_tmp  [MTOT * D_MODEL];
__device__ __half g_hH   [MTOT * DFF];          // relu(ffn1), fp16
__device__ __half g_xH   [MTOT * D_MODEL];      // x, fp16
__device__ __half g_wqkvH[3 * D_MODEL * D_MODEL];   // [K][N] (no transpose)
__device__ __half g_woH  [D_MODEL * D_MODEL];
__device__ __half g_w1H  [D_MODEL * DFF];
__device__ __half g_w2H  [DFF * D_MODEL];

// ---------------------------------------------------------------------------
// helpers
// ---------------------------------------------------------------------------
__device__ __forceinline__ void mma_f16(float c[4], const uint32_t a[4],
                                        const uint32_t b[2]) {
    asm("mma.sync.aligned.m16n8k16.row.col.f32.f16.f16.f32 "
        "{%0,%1,%2,%3}, {%4,%5,%6,%7}, {%8,%9}, {%0,%1,%2,%3};"
        : "+f"(c[0]), "+f"(c[1]), "+f"(c[2]), "+f"(c[3])
        : "r"(a[0]), "r"(a[1]), "r"(a[2]), "r"(a[3]), "r"(b[0]), "r"(b[1]));
}

__device__ __forceinline__ void ldm_x4(uint32_t r[4], uint32_t addr) {
    asm volatile("ldmatrix.sync.aligned.m8n8.x4.shared.b16 {%0,%1,%2,%3}, [%4];"
                 : "=r"(r[0]), "=r"(r[1]), "=r"(r[2]), "=r"(r[3]) : "r"(addr));
}
__device__ __forceinline__ void ldm_x4_t(uint32_t r[4], uint32_t addr) {
    asm volatile("ldmatrix.sync.aligned.m8n8.x4.trans.shared.b16 {%0,%1,%2,%3}, [%4];"
                 : "=r"(r[0]), "=r"(r[1]), "=r"(r[2]), "=r"(r[3]) : "r"(addr));
}

__device__ __forceinline__ void cp16(uint32_t saddr, const void* gptr) {
    asm volatile("cp.async.cg.shared.global [%0], [%1], 16;"
                 :: "r"(saddr), "l"(gptr));
}
__device__ __forceinline__ void cp_commit() { asm volatile("cp.async.commit_group;"); }
__device__ __forceinline__ void cp_wait1()  { asm volatile("cp.async.wait_group 1;"); }

// paired fp16 exp2 on MUFU: one instruction for two values
__device__ __forceinline__ uint32_t ex2_f16x2(float lo, float hi) {
    __half2 h = __floats2half2_rn(lo, hi);
    uint32_t r;
    asm("ex2.approx.f16x2 %0, %1;" : "=r"(r) : "r"(*(uint32_t*)&h));
    return r;
}

// ---------------------------------------------------------------------------
// fp16 tensor-core GEMM — unchanged from R10 (proven).
// ---------------------------------------------------------------------------
#define KTILE 64
#define GPA 72
#define GPB 136
#define ATILE_B (128 * GPA * 2)
#define BTILE_B (KTILE * GPB * 2)
#define STG_B   (ATILE_B + BTILE_B)
#define GEMM_SMEM (3 * STG_B)        // 107520

template <int EPI, int OUTH>
__device__ __forceinline__ void gemm_body(
    const __half* __restrict__ A, const __half* __restrict__ W,
    const float* __restrict__ bias, const float* __restrict__ res,
    void* __restrict__ Cv, int N, int K, int bm, int bn, float oscale)
{
    extern __shared__ uint32_t gsm[];

    const int tid  = threadIdx.x;
    const int wid  = tid >> 5;
    const int lane = tid & 31;
    const int g    = lane >> 2;
    const int t    = lane & 3;
    const int wm   = (wid & 1) * 64;
    const int wn   = (wid >> 1) * 32;

    float acc[4][4][4];
#pragma unroll
    for (int i = 0; i < 4; i++)
#pragma unroll
        for (int j = 0; j < 4; j++)
#pragma unroll
            for (int e = 0; e < 4; e++) acc[i][j][e] = 0.f;

    const uint32_t sbase = (uint32_t)__cvta_generic_to_shared(gsm);

#define GI(slot, kt_)                                                          \
    {                                                                          \
        const uint32_t so_ = (uint32_t)(slot) * STG_B;                         \
        const int k0_ = (kt_) * KTILE;                                         \
        _Pragma("unroll")                                                      \
        for (int i = 0; i < 4; i++) {                                          \
            const int idx = tid + 256 * i;                                     \
            const int ar = idx >> 3, ac = idx & 7;                             \
            cp16(sbase + so_ + (uint32_t)(ar * GPA + ac * 8) * 2,              \
                 A + (size_t)(bm + ar) * K + k0_ + ac * 8);                    \
        }                                                                      \
        _Pragma("unroll")                                                      \
        for (int i = 0; i < 4; i++) {                                          \
            const int idx = tid + 256 * i;                                     \
            const int br = idx >> 4, bc = idx & 15;                            \
            cp16(sbase + so_ + ATILE_B + (uint32_t)(br * GPB + bc * 8) * 2,    \
                 W + (size_t)(k0_ + br) * N + bn + bc * 8);                    \
        }                                                                      \
    }

    const int lr = lane & 7, sel = lane >> 3;
    const int aro = (sel & 1) * 8 + lr, aco = (sel >> 1) * 8;
    uint32_t a_lm[4];
#pragma unroll
    for (int mt = 0; mt < 4; mt++)
        a_lm[mt] = sbase + (uint32_t)((wm + mt * 16 + aro) * GPA + aco) * 2;
    const int vro = (sel & 1) * 8 + lr, vco = (sel >> 1) * 8;
    uint32_t b_lm[2];
#pragma unroll
    for (int p = 0; p < 2; p++)
        b_lm[p] = sbase + ATILE_B +
                  (uint32_t)(vro * GPB + wn + p * 16 + vco) * 2;

    const int nk = K / KTILE;
    GI(0, 0) cp_commit();
    GI(1, 1) cp_commit();

    int csl = 0, isl = 2;
    for (int kt = 0; kt < nk; kt++) {
        cp_wait1();
        __syncthreads();
        if (kt + 2 < nk) { GI(isl, kt + 2) isl = (isl == 2) ? 0 : isl + 1; }
        cp_commit();

        const uint32_t so = (uint32_t)csl * STG_B;
#pragma unroll
        for (int ks = 0; ks < 4; ks++) {
            uint32_t af[4][4];
#pragma unroll
            for (int mt = 0; mt < 4; mt++)
                ldm_x4(af[mt], a_lm[mt] + so + ks * 32);
            uint32_t bf[2][4];
            ldm_x4_t(bf[0], b_lm[0] + so + ks * (16 * GPB * 2));
            ldm_x4_t(bf[1], b_lm[1] + so + ks * (16 * GPB * 2));
#pragma unroll
            for (int mt = 0; mt < 4; mt++)
#pragma unroll
                for (int nt = 0; nt < 4; nt++)
                    mma_f16(acc[mt][nt], af[mt], &bf[nt >> 1][(nt & 1) * 2]);
        }
        csl = (csl == 2) ? 0 : csl + 1;
    }
#undef GI

#pragma unroll
    for (int mt = 0; mt < 4; mt++) {
        const int r = bm + wm + mt * 16 + g;
#pragma unroll
        for (int nt = 0; nt < 4; nt++) {
            const int c = bn + wn + nt * 8 + 2 * t;
            const float2 bb = *(const float2*)(bias + c);
            float2 v0, v1;
            v0.x = (acc[mt][nt][0] + bb.x) * oscale;
            v0.y = (acc[mt][nt][1] + bb.y) * oscale;
            v1.x = (acc[mt][nt][2] + bb.x) * oscale;
            v1.y = (acc[mt][nt][3] + bb.y) * oscale;
            if (EPI == 1) {
                v0.x = fmaxf(v0.x, 0.f); v0.y = fmaxf(v0.y, 0.f);
                v1.x = fmaxf(v1.x, 0.f); v1.y = fmaxf(v1.y, 0.f);
            }
            if (EPI == 2) {
                const float2 q0r = *(const float2*)(res + (size_t)r * N + c);
                const float2 q1r = *(const float2*)(res + (size_t)(r + 8) * N + c);
                v0.x += q0r.x; v0.y += q0r.y;
                v1.x += q1r.x; v1.y += q1r.y;
            }
            if (OUTH) {
                __half* C = (__half*)Cv;
                *(__half2*)(C + (size_t)r * N + c)       = __floats2half2_rn(v0.x, v0.y);
                *(__half2*)(C + (size_t)(r + 8) * N + c) = __floats2half2_rn(v1.x, v1.y);
            } else {
                float* C = (float*)Cv;
                *(float2*)(C + (size_t)r * N + c)       = v0;
                *(float2*)(C + (size_t)(r + 8) * N + c) = v1;
            }
        }
    }
}

template <int EPI, int OUTH>
__global__ __launch_bounds__(256, 2)
void gemm_tc(const __half* __restrict__ A, const __half* __restrict__ W,
             const float* __restrict__ bias, const float* __restrict__ res,
             void* __restrict__ C, int N, int K)
{
    gemm_body<EPI, OUTH>(A, W, bias, res, C, N, K,
                         blockIdx.y * 128, blockIdx.x * 128, 1.f);
}

// fused QKV: gridDim.z = 3; Q pre-scaled by log2e/sqrt(DK) (log2-domain scores)
__global__ __launch_bounds__(256, 2)
void qkv_tc(const __half* __restrict__ xH, const __half* __restrict__ wqkvH,
            const float* __restrict__ bq, const float* __restrict__ bk,
            const float* __restrict__ bv, __half* __restrict__ qkvH)
{
    const int z = blockIdx.z;
    const float* bias = (z == 0) ? bq : (z == 1) ? bk : bv;
    gemm_body<0, 1>(xH, wqkvH + (size_t)z * D_MODEL * D_MODEL, bias, nullptr,
                    qkvH + (size_t)z * MTOT * D_MODEL, D_MODEL, D_MODEL,
                    blockIdx.y * 128, blockIdx.x * 128,
                    (z == 0) ? 0.125f * 1.4426950408889634f : 1.f);
}

// ---------------------------------------------------------------------------
// Fused pre-pass: ALL fp32 -> fp16 converts in one launch. (R10-proven)
// ---------------------------------------------------------------------------
__global__ __launch_bounds__(256)
void cvt_all(const float* __restrict__ x,  const float* __restrict__ wq,
             const float* __restrict__ wk, const float* __restrict__ wv,
             const float* __restrict__ wo, const float* __restrict__ w1,
             const float* __restrict__ w2,
             __half* __restrict__ xH, __half* __restrict__ wqkvH,
             __half* __restrict__ woH, __half* __restrict__ w1H,
             __half* __restrict__ w2H)
{
    const int bid = blockIdx.x;
    const float* src;
    __half* dst;
    int off;
    if      (bid < 4096)  { src = x;  dst = xH;                      off = bid; }
    else if (bid < 5120)  { src = wq; dst = wqkvH;                   off = bid - 4096; }
    else if (bid < 6144)  { src = wk; dst = wqkvH + D_MODEL*D_MODEL; off = bid - 5120; }
    else if (bid < 7168)  { src = wv; dst = wqkvH + 2*D_MODEL*D_MODEL; off = bid - 6144; }
    else if (bid < 8192)  { src = wo; dst = woH;                     off = bid - 7168; }
    else if (bid < 12288) { src = w1; dst = w1H;                     off = bid - 8192; }
    else                  { src = w2; dst = w2H;                     off = bid - 12288; }

    const int i = off * 256 + threadIdx.x;
    float4 v = ((const float4*)src)[i];
    __half2 h0 = __floats2half2_rn(v.x, v.y);
    __half2 h1 = __floats2half2_rn(v.z, v.w);
    uint2 u;
    u.x = *(uint32_t*)&h0;
    u.y = *(uint32_t*)&h1;
    ((uint2*)dst)[i] = u;
}

// ---------------------------------------------------------------------------
// fp16 flash attention, log2-domain softmax.
// New in R12: P never touches smem — the S-accumulator output pairs ARE the
// PV A-fragments (m16n8k16 layout identity); row sums come from an extra mma
// against a constant all-ones B fragment (P @ 1 -> every column = row sum),
// removing the P stores, PV ldmatrix, rs cvt/add chain and shfl reductions.
// ---------------------------------------------------------------------------
#define AQT 128
#define AKT 64
#define PH  72
#define QH  (AQT * PH)
#define KVST (2 * AKT * PH)
#define ATTN_SMEM ((QH + 3 * KVST) * 2)   // 73728 bytes

__global__ __launch_bounds__(256, 2)
void attn_tc(const __half* __restrict__ Q, const __half* __restrict__ K,
             const __half* __restrict__ V, __half* __restrict__ O)
{
    extern __shared__ uint32_t asmem[];
    __half* smh = (__half*)asmem;

    const int tid  = threadIdx.x;
    const int wid  = tid >> 5;
    const int lane = tid & 31;
    const int g    = lane >> 2;
    const int t    = lane & 3;
    const int bh   = blockIdx.y;
    const int b    = bh >> 4;
    const int h    = bh & 15;
    const int q0   = blockIdx.x * AQT;
    const size_t base = (size_t)b * SEQ * D_MODEL + (size_t)h * DK;

#pragma unroll
    for (int e = 0; e < 4; e++) {
        int idx = tid + 256 * e;
        int r = idx >> 3, ch = idx & 7;
        ((uint4*)(smh + r * PH))[ch] =
            *((const uint4*)(Q + base + (size_t)(q0 + r) * D_MODEL) + ch);
    }

    float m0 = -1e30f, m1 = -1e30f, l0 = 0.f, l1 = 0.f;
    float oacc[8][4];
#pragma unroll
    for (int nt = 0; nt < 8; nt++)
#pragma unroll
        for (int e = 0; e < 4; e++) oacc[nt][e] = 0.f;

    const int qrow = wid * 16;

    const int kvr = tid >> 3, kvc = tid & 7;
    const uint32_t sb = (uint32_t)__cvta_generic_to_shared(asmem);
    const uint32_t kS = sb + (uint32_t)QH * 2 + (uint32_t)(kvr * PH + kvc * 8) * 2;

#define CPKV(slot, kt_)                                                        \
    {                                                                          \
        const uint32_t so_ = (uint32_t)(slot) * (KVST * 2);                    \
        const size_t gr0 = base + (size_t)((kt_) * AKT + kvr) * D_MODEL;       \
        const size_t gr1 = gr0 + (size_t)32 * D_MODEL;                         \
        cp16(kS + so_, K + gr0 + kvc * 8);                                     \
        cp16(kS + so_ + 32 * PH * 2, K + gr1 + kvc * 8);                       \
        cp16(kS + so_ + AKT * PH * 2, V + gr0 + kvc * 8);                      \
        cp16(kS + so_ + AKT * PH * 2 + 32 * PH * 2, V + gr1 + kvc * 8);        \
    }

    const int lr = lane & 7, sel = lane >> 3;
    const int aro = (sel & 1) * 8 + lr, aco = (sel >> 1) * 8;
    const int bro = (sel >> 1) * 8 + lr, bco = (sel & 1) * 8;
    const int vro = (sel & 1) * 8 + lr, vco = (sel >> 1) * 8;
    const uint32_t q_lm = sb + (uint32_t)((qrow + aro) * PH + aco) * 2;
    uint32_t k_lm[4], v_lm[4];
#pragma unroll
    for (int p = 0; p < 4; p++) {
        k_lm[p] = (uint32_t)((p * 16 + bro) * PH + bco) * 2;
        v_lm[p] = (uint32_t)(vro * PH + p * 16 + vco) * 2;
    }

    // all-ones B fragment for row-sum mma (half 1.0 = 0x3C00)
    const uint32_t ones2[2] = { 0x3C003C00u, 0x3C003C00u };

    const int nk = SEQ / AKT;
    CPKV(0, 0) cp_commit();
    CPKV(1, 1) cp_commit();

    int csl = 0, isl = 2;
    for (int kt = 0; kt < nk; kt++) {
        cp_wait1();
        __syncthreads();
        if (kt + 2 < nk) { CPKV(isl, kt + 2) isl = (isl == 2) ? 0 : isl + 1; }
        cp_commit();

        const uint32_t kb = (uint32_t)QH * 2 + (uint32_t)csl * (KVST * 2);
        const uint32_t vb = kb + (uint32_t)(AKT * PH) * 2;

        // ---- S(log2) = Q K^T ----
        float sacc[8][4];
#pragma unroll
        for (int nt = 0; nt < 8; nt++)
#pragma unroll
            for (int e = 0; e < 4; e++) sacc[nt][e] = 0.f;

#pragma unroll
        for (int ks = 0; ks < 4; ks++) {
            uint32_t a[4];
            ldm_x4(a, q_lm + ks * 32);
            uint32_t kf[4][4];
#pragma unroll
            for (int p = 0; p < 4; p++)
                ldm_x4(kf[p], sb + kb + k_lm[p] + ks * 32);
#pragma unroll
            for (int nt = 0; nt < 8; nt++)
                mma_f16(sacc[nt], a, &kf[nt >> 1][(nt & 1) * 2]);
        }

        // ---- online softmax (log2 domain, fp16x2 exp2, P kept in regs) ----
        float rmax0 = -1e30f, rmax1 = -1e30f;
#pragma unroll
        for (int nt = 0; nt < 8; nt++) {
            rmax0 = fmaxf(rmax0, fmaxf(sacc[nt][0], sacc[nt][1]));
            rmax1 = fmaxf(rmax1, fmaxf(sacc[nt][2], sacc[nt][3]));
        }
        rmax0 = fmaxf(rmax0, __shfl_xor_sync(0xffffffffu, rmax0, 1));
        rmax0 = fmaxf(rmax0, __shfl_xor_sync(0xffffffffu, rmax0, 2));
        rmax1 = fmaxf(rmax1, __shfl_xor_sync(0xffffffffu, rmax1, 1));
        rmax1 = fmaxf(rmax1, __shfl_xor_sync(0xffffffffu, rmax1, 2));

        const float nm0 = fmaxf(m0, rmax0);
        const float nm1 = fmaxf(m1, rmax1);
        const float sc0 = exp2f(m0 - nm0);
        const float sc1 = exp2f(m1 - nm1);

        uint32_t pp0[8], pp1[8];
#pragma unroll
        for (int nt = 0; nt < 8; nt++) {
            pp0[nt] = ex2_f16x2(sacc[nt][0] - nm0, sacc[nt][1] - nm0);
            pp1[nt] = ex2_f16x2(sacc[nt][2] - nm1, sacc[nt][3] - nm1);
        }

        // row sums via mma: lacc = P @ ones (every column = row sum)
        float lacc[4] = {0.f, 0.f, 0.f, 0.f};
#pragma unroll
        for (int ks = 0; ks < 4; ks++) {
            const uint32_t a[4] = { pp0[2 * ks], pp1[2 * ks],
                                    pp0[2 * ks + 1], pp1[2 * ks + 1] };
            mma_f16(lacc, a, ones2);
        }

        m0 = nm0; m1 = nm1;
        l0 = l0 * sc0 + lacc[0];
        l1 = l1 * sc1 + lacc[2];
#pragma unroll
        for (int nt = 0; nt < 8; nt++) {
            oacc[nt][0] *= sc0; oacc[nt][1] *= sc0;
            oacc[nt][2] *= sc1; oacc[nt][3] *= sc1;
        }

        // ---- O += P V : P a-frags direct from registers, V via ldm.trans ----
#pragma unroll
        for (int ks = 0; ks < 4; ks++) {
            const uint32_t a[4] = { pp0[2 * ks], pp1[2 * ks],
                                    pp0[2 * ks + 1], pp1[2 * ks + 1] };
            uint32_t vf[4][4];
#pragma unroll
            for (int p = 0; p < 4; p++)
                ldm_x4_t(vf[p], sb + vb + v_lm[p] + ks * (16 * PH * 2));
#pragma unroll
            for (int nt = 0; nt < 8; nt++)
                mma_f16(oacc[nt], a, &vf[nt >> 1][(nt & 1) * 2]);
        }

        csl = (csl == 2) ? 0 : csl + 1;
    }
#undef CPKV

    const float il0 = 1.f / l0;
    const float il1 = 1.f / l1;
#pragma unroll
    for (int nt = 0; nt < 8; nt++) {
        const int c = nt * 8 + 2 * t;
        __half2 u0 = __floats2half2_rn(oacc[nt][0] * il0, oacc[nt][1] * il0);
        __half2 u1 = __floats2half2_rn(oacc[nt][2] * il1, oacc[nt][3] * il1);
        *(__half2*)(O + base + (size_t)(q0 + qrow + g    ) * D_MODEL + c) = u0;
        *(__half2*)(O + base + (size_t)(q0 + qrow + g + 8) * D_MODEL + c) = u1;
    }
}

// ---------------------------------------------------------------------------
// LayerNorm over last dim (1024), float4 path; optional fp16 copy output.
// ---------------------------------------------------------------------------
__global__ __launch_bounds__(256)
void ln_kernel(const float* __restrict__ X, const float* __restrict__ g,
               const float* __restrict__ b, float* __restrict__ Y,
               __half* __restrict__ Yh)
{
    const int row = blockIdx.x;
    const int tid = threadIdx.x;
    const float4 v = *((const float4*)(X + (size_t)row * D_MODEL) + tid);

    float s  = v.x + v.y + v.z + v.w;
    float s2 = v.x * v.x + v.y * v.y + v.z * v.z + v.w * v.w;
#pragma unroll
    for (int off = 16; off; off >>= 1) {
        s  += __shfl_xor_sync(0xffffffffu, s,  off);
        s2 += __shfl_xor_sync(0xffffffffu, s2, off);
    }
    __shared__ float rs[8], rs2[8];
    const int w = tid >> 5, lane = tid & 31;
    if (lane == 0) { rs[w] = s; rs2[w] = s2; }
    __syncthreads();
    s = 0.f; s2 = 0.f;
#pragma unroll
    for (int i = 0; i < 8; i++) { s += rs[i]; s2 += rs2[i]; }

    const float mean = s * (1.f / D_MODEL);
    const float var  = s2 * (1.f / D_MODEL) - mean * mean;
    const float rstd = rsqrtf(var + 1e-5f);

    const float4 gg = *((const float4*)g + tid);
    const float4 bb = *((const float4*)b + tid);
    float4 y;
    y.x = (v.x - mean) * rstd * gg.x + bb.x;
    y.y = (v.y - mean) * rstd * gg.y + bb.y;
    y.z = (v.z - mean) * rstd * gg.z + bb.z;
    y.w = (v.w - mean) * rstd * gg.w + bb.w;
    *((float4*)(Y + (size_t)row * D_MODEL) + tid) = y;
    if (Yh) {
        __half2 h0 = __floats2half2_rn(y.x, y.y);
        __half2 h1 = __floats2half2_rn(y.z, y.w);
        uint2 u;
        u.x = *(uint32_t*)&h0;
        u.y = *(uint32_t*)&h1;
        *((uint2*)(Yh + (size_t)row * D_MODEL) + tid) = u;
    }
}

// ---------------------------------------------------------------------------
// Launch
// ---------------------------------------------------------------------------
extern "C" void kernel_launch(void* const* d_in, const int* in_sizes, int n_in,
                              void* d_out, int out_size)
{
    const float* x     = (const float*)d_in[0];
    const float* wq    = (const float*)d_in[1];
    const float* bq    = (const float*)d_in[2];
    const float* wk    = (const float*)d_in[3];
    const float* bk    = (const float*)d_in[4];
    const float* wv    = (const float*)d_in[5];
    const float* bv    = (const float*)d_in[6];
    const float* wo    = (const float*)d_in[7];
    const float* bo    = (const float*)d_in[8];
    const float* ln1_g = (const float*)d_in[9];
    const float* ln1_b = (const float*)d_in[10];
    const float* ln2_g = (const float*)d_in[11];
    const float* ln2_b = (const float*)d_in[12];
    const float* w1    = (const float*)d_in[13];
    const float* b1    = (const float*)d_in[14];
    const float* w2    = (const float*)d_in[15];
    const float* b2    = (const float*)d_in[16];
    float* out = (float*)d_out;

    float *x1, *tmp;
    __half *qkvH, *attnH, *x1H, *hH, *xH, *wqkvH, *woH, *w1H, *w2H;
    cudaGetSymbolAddress((void**)&qkvH,  g_qkvH);
    cudaGetSymbolAddress((void**)&attnH, g_attnH);
    cudaGetSymbolAddress((void**)&x1,    g_x1);
    cudaGetSymbolAddress((void**)&x1H,   g_x1H);
    cudaGetSymbolAddress((void**)&tmp,   g_tmp);
    cudaGetSymbolAddress((void**)&hH,    g_hH);
    cudaGetSymbolAddress((void**)&xH,    g_xH);
    cudaGetSymbolAddress((void**)&wqkvH, g_wqkvH);
    cudaGetSymbolAddress((void**)&woH,   g_woH);
    cudaGetSymbolAddress((void**)&w1H,   g_w1H);
    cudaGetSymbolAddress((void**)&w2H,   g_w2H);

    cudaFuncSetAttribute(attn_tc, cudaFuncAttributeMaxDynamicSharedMemorySize,
                         ATTN_SMEM);
    cudaFuncSetAttribute(qkv_tc, cudaFuncAttributeMaxDynamicSharedMemorySize,
                         GEMM_SMEM);
    cudaFuncSetAttribute(gemm_tc<2, 0>, cudaFuncAttributeMaxDynamicSharedMemorySize,
                         GEMM_SMEM);
    cudaFuncSetAttribute(gemm_tc<1, 1>, cudaFuncAttributeMaxDynamicSharedMemorySize,
                         GEMM_SMEM);

    const dim3 blk(256);

    // fused pre-pass: all fp32 -> fp16 converts in one launch
    cvt_all<<<16384, blk>>>(x, wq, wk, wv, wo, w1, w2,
                            xH, wqkvH, woH, w1H, w2H);

    // QKV (fused, z = 0/1/2), Q pre-scaled by log2e/8
    qkv_tc<<<dim3(D_MODEL / 128, MTOT / 128, 3), blk, GEMM_SMEM>>>(
        xH, wqkvH, bq, bk, bv, qkvH);

    // attention
    attn_tc<<<dim3(SEQ / AQT, BATCH * NH), blk, ATTN_SMEM>>>(
        qkvH, qkvH + (size_t)MTOT * D_MODEL, qkvH + (size_t)2 * MTOT * D_MODEL,
        attnH);

    // O-proj + residual -> LN1
    gemm_tc<2, 0><<<dim3(D_MODEL / 128, MTOT / 128), blk, GEMM_SMEM>>>(
        attnH, woH, bo, x, tmp, D_MODEL, D_MODEL);
    ln_kernel<<<MTOT, blk>>>(tmp, ln1_g, ln1_b, x1, x1H);

    // FFN
    gemm_tc<1, 1><<<dim3(DFF / 128, MTOT / 128), blk, GEMM_SMEM>>>(
        x1H, w1H, b1, nullptr, hH, DFF, D_MODEL);
    gemm_tc<2, 0><<<dim3(D_MODEL / 128, MTOT / 128), blk, GEMM_SMEM>>>(
        hH, w2H, b2, x1, tmp, D_MODEL, DFF);
    ln_kernel<<<MTOT, blk>>>(tmp, ln2_g, ln2_b, out, nullptr);
}